// round 1
// baseline (speedup 1.0000x reference)
#include <cuda_runtime.h>
#include <cstdint>
#include <cstddef>

// Problem constants
#define B_SZ   2048
#define I_SZ   256
#define P_SZ   257        // I + 1 (with ones column)
#define FLATK  66049      // 257*257
#define N1     512

// Kernel-1 tiling
#define BM     128
#define BN     64
#define PJ     288        // padded j extent: 9 tiles * 32
#define CSTR   296        // c_s row stride (floats), 8y+x bank pattern -> conflict free
#define WK     32         // K per pipeline stage
#define WSTR   72         // W tile row stride (floats), conflict-free B-frag LDS
#define G_I    2          // i's processed per group (two accumulator sets)
#define NIG    129        // ceil(257/2): i = 2*ig + g, padded with a=0 at i=257
#define NKT    9          // j tiles per i (9*32 = 288 >= 257)
#define NSTAGE (NIG*NKT)  // 1161 pipeline stages

// Scratch for intermediate H = relu(fusion@W1 + b1)  (4 MB, static: allowed)
__device__ float g_H[(size_t)B_SZ * N1];

__device__ __forceinline__ uint32_t f2tf(float x) {
    uint32_t u;
    asm("cvt.rna.tf32.f32 %0, %1;" : "=r"(u) : "f"(x));
    return u;
}

__device__ __forceinline__ void mma8(float* d, uint32_t a0, uint32_t a1, uint32_t a2, uint32_t a3,
                                     uint32_t b0, uint32_t b1) {
    asm volatile(
        "mma.sync.aligned.m16n8k8.row.col.f32.tf32.tf32.f32 "
        "{%0,%1,%2,%3}, {%4,%5,%6,%7}, {%8,%9}, {%0,%1,%2,%3};"
        : "+f"(d[0]), "+f"(d[1]), "+f"(d[2]), "+f"(d[3])
        : "r"(a0), "r"(a1), "r"(a2), "r"(a3), "r"(b0), "r"(b1));
}

__device__ __forceinline__ void cpa16(uint32_t smem, const void* g) {
    asm volatile("cp.async.cg.shared.global [%0], [%1], 16;" :: "r"(smem), "l"(g));
}
__device__ __forceinline__ void cpcommit() { asm volatile("cp.async.commit_group;"); }
__device__ __forceinline__ void cpwait1()  { asm volatile("cp.async.wait_group 1;"); }

// ---------------------------------------------------------------------------
// Kernel 1: H = relu( (a kr c) @ W1 + b1 )
//   h[m,n] = sum_i a_ext[m,i] * ( sum_j c_ext[m,j] * W1[i*257+j, n] )
// CTA: 128x64 output tile, 256 threads = 8 warps (4 m-warps x 2 n-warps),
// warp tile 32x32 via m16n8k8 tf32 mma. c-tile resident in SMEM (tf32),
// W1 streamed through a 3-deep cp.async ring (32 rows x 64 cols per i).
// ---------------------------------------------------------------------------
extern __shared__ float smem1[];

__global__ void __launch_bounds__(256, 1)
fused_k1(const float* __restrict__ inp1, const float* __restrict__ inp2,
         const float* __restrict__ W1, const float* __restrict__ b1)
{
    float* c_s = smem1;                       // [BM][CSTR]
    float* w_s = smem1 + BM * CSTR;           // [3][G_I][WK*WSTR]

    const int tid  = threadIdx.x;
    const int lane = tid & 31;
    const int wid  = tid >> 5;
    const int wm   = wid & 3;                 // m-warp 0..3
    const int wn   = wid >> 2;                // n-warp 0..1
    const int m0   = blockIdx.y * BM;
    const int n0   = blockIdx.x * BN;

    // ---- stage c tile (with ones column at j=256, zeros beyond) as tf32 ----
    for (int idx = tid; idx < BM * PJ; idx += 256) {
        int m = idx / PJ, j = idx - m * PJ;
        float v = (j < I_SZ) ? inp2[(size_t)(m0 + m) * I_SZ + j]
                             : (j == I_SZ ? 1.0f : 0.0f);
        c_s[m * CSTR + j] = __uint_as_float(f2tf(v));
    }
    __syncthreads();

    // ---- W1 stage loader: rows i_g*257 + j0 + r  (clamped; A=0 covers pads)
    auto issueW = [&](int s) {
        int ig2 = s / NKT, kt2 = s - ig2 * NKT;
        int j0  = kt2 * WK;
        float* dst = w_s + (s % 3) * (G_I * WK * WSTR);
        #pragma unroll
        for (int t = 0; t < 4; ++t) {
            int idx  = tid + t * 256;         // 0..1023
            int rall = idx >> 4;              // 0..63
            int g    = rall >> 5;             // 0..1
            int r    = rall & 31;             // row within tile
            int cg   = idx & 15;              // 4-float column group
            int i_g  = ig2 * G_I + g;
            int row  = i_g * P_SZ + j0 + r;
            if (row > FLATK - 1) row = FLATK - 1;   // value irrelevant (A=0)
            const float* src = W1 + (size_t)row * N1 + n0 + cg * 4;
            uint32_t sm = (uint32_t)__cvta_generic_to_shared(
                dst + g * (WK * WSTR) + r * WSTR + cg * 4);
            cpa16(sm, src);
        }
    };

    issueW(0); cpcommit();
    issueW(1); cpcommit();

    float h_acc[2][4][4];
    #pragma unroll
    for (int mt = 0; mt < 2; ++mt)
        #pragma unroll
        for (int nt = 0; nt < 4; ++nt)
            #pragma unroll
            for (int r = 0; r < 4; ++r) h_acc[mt][nt][r] = 0.0f;

    const int mrb = wm * 32 + (lane >> 2);    // base A row for this thread

    for (int ig = 0; ig < NIG; ++ig) {
        // prefetch a-scales for this i-group (full fp32; i==256 -> 1, i>256 -> 0)
        float av[2][4];
        #pragma unroll
        for (int g = 0; g < 2; ++g) {
            int i = ig * G_I + g;
            #pragma unroll
            for (int r = 0; r < 4; ++r) {
                int m = m0 + wm * 32 + (r >> 1) * 16 + (r & 1) * 8 + (lane >> 2);
                av[g][r] = (i < I_SZ) ? inp1[(size_t)m * I_SZ + i]
                                      : (i == I_SZ ? 1.0f : 0.0f);
            }
        }

        float tmp[2][2][4][4];
        #pragma unroll
        for (int g = 0; g < 2; ++g)
            #pragma unroll
            for (int mt = 0; mt < 2; ++mt)
                #pragma unroll
                for (int nt = 0; nt < 4; ++nt)
                    #pragma unroll
                    for (int r = 0; r < 4; ++r) tmp[g][mt][nt][r] = 0.0f;

        for (int kt = 0; kt < NKT; ++kt) {
            int s = ig * NKT + kt;
            cpwait1();            // stage s data landed (own groups)
            __syncthreads();      // ...for everyone; stage s-1 reads all done
            int s2 = s + 2;
            if (s2 < NSTAGE) issueW(s2);   // into buf[(s+2)%3] == buf[(s-1)%3]
            cpcommit();

            int j0 = kt * WK;

            // A fragments from c_s (already tf32) — reused across both g's
            uint32_t Af[4][8];
            #pragma unroll
            for (int ks = 0; ks < 4; ++ks)
                #pragma unroll
                for (int mt = 0; mt < 2; ++mt)
                    #pragma unroll
                    for (int q = 0; q < 4; ++q) {
                        int row = mrb + mt * 16 + (q & 1) * 8;
                        int col = j0 + ks * 8 + (lane & 3) + ((q >> 1) << 2);
                        Af[ks][mt * 4 + q] = __float_as_uint(c_s[row * CSTR + col]);
                    }

            const float* wb = w_s + (s % 3) * (G_I * WK * WSTR);
            #pragma unroll
            for (int g = 0; g < 2; ++g) {
                const float* wg = wb + g * (WK * WSTR);
                #pragma unroll
                for (int ks = 0; ks < 4; ++ks) {
                    uint32_t bb[4][2];
                    #pragma unroll
                    for (int nt = 0; nt < 4; ++nt) {
                        int col = wn * 32 + nt * 8 + (lane >> 2);
                        int k   = ks * 8 + (lane & 3);
                        bb[nt][0] = f2tf(wg[k * WSTR + col]);
                        bb[nt][1] = f2tf(wg[(k + 4) * WSTR + col]);
                    }
                    #pragma unroll
                    for (int mt = 0; mt < 2; ++mt)
                        #pragma unroll
                        for (int nt = 0; nt < 4; ++nt)
                            mma8(tmp[g][mt][nt],
                                 Af[ks][mt * 4 + 0], Af[ks][mt * 4 + 1],
                                 Af[ks][mt * 4 + 2], Af[ks][mt * 4 + 3],
                                 bb[nt][0], bb[nt][1]);
                }
            }
        }

        // scale by a[m,i] (fp32) and accumulate
        #pragma unroll
        for (int g = 0; g < 2; ++g)
            #pragma unroll
            for (int mt = 0; mt < 2; ++mt)
                #pragma unroll
                for (int nt = 0; nt < 4; ++nt)
                    #pragma unroll
                    for (int r = 0; r < 4; ++r)
                        h_acc[mt][nt][r] += av[g][mt * 2 + (r >> 1)] * tmp[g][mt][nt][r];
    }

    // epilogue: + b1, relu, write H
    #pragma unroll
    for (int mt = 0; mt < 2; ++mt)
        #pragma unroll
        for (int nt = 0; nt < 4; ++nt) {
            int n_base = n0 + wn * 32 + nt * 8 + (lane & 3) * 2;
            float bv0 = b1[n_base], bv1 = b1[n_base + 1];
            #pragma unroll
            for (int h = 0; h < 2; ++h) {
                int m = m0 + wm * 32 + mt * 16 + h * 8 + (lane >> 2);
                float v0 = fmaxf(h_acc[mt][nt][h * 2 + 0] + bv0, 0.0f);
                float v1 = fmaxf(h_acc[mt][nt][h * 2 + 1] + bv1, 0.0f);
                *(float2*)&g_H[(size_t)m * N1 + n_base] = make_float2(v0, v1);
            }
        }
}

// ---------------------------------------------------------------------------
// Kernel 2: out = relu( H @ W2 + b2 )   (exact fp32 SIMT; tiny vs kernel 1)
// CTA 64x64, 256 threads, thread tile 4x4, BK=16.
// ---------------------------------------------------------------------------
__global__ void __launch_bounds__(256)
fused_k2(const float* __restrict__ W2, const float* __restrict__ b2,
         float* __restrict__ out)
{
    __shared__ float As[16][68];   // transposed A tile: As[k][m]
    __shared__ float Bs[16][68];

    const int tid = threadIdx.x;
    const int tx = tid & 15, ty = tid >> 4;
    const int m0 = blockIdx.y * 64, n0 = blockIdx.x * 64;

    float acc[4][4];
    #pragma unroll
    for (int i = 0; i < 4; ++i)
        #pragma unroll
        for (int j = 0; j < 4; ++j) acc[i][j] = 0.0f;

    for (int k0 = 0; k0 < N1; k0 += 16) {
        int am = tid >> 2, akq = tid & 3;
        float4 va = *(const float4*)&g_H[(size_t)(m0 + am) * N1 + k0 + akq * 4];
        int bk = tid >> 4, bng = tid & 15;
        float4 vb = *(const float4*)&W2[(size_t)(k0 + bk) * N1 + n0 + bng * 4];
        __syncthreads();
        As[akq * 4 + 0][am] = va.x;
        As[akq * 4 + 1][am] = va.y;
        As[akq * 4 + 2][am] = va.z;
        As[akq * 4 + 3][am] = va.w;
        *(float4*)&Bs[bk][bng * 4] = vb;
        __syncthreads();
        #pragma unroll
        for (int kk = 0; kk < 16; ++kk) {
            float4 a = *(const float4*)&As[kk][ty * 4];
            float4 b = *(const float4*)&Bs[kk][tx * 4];
            float aa[4] = {a.x, a.y, a.z, a.w};
            float bb[4] = {b.x, b.y, b.z, b.w};
            #pragma unroll
            for (int i = 0; i < 4; ++i)
                #pragma unroll
                for (int j = 0; j < 4; ++j) acc[i][j] += aa[i] * bb[j];
        }
    }

    float bv[4];
    #pragma unroll
    for (int j = 0; j < 4; ++j) bv[j] = b2[n0 + tx * 4 + j];
    #pragma unroll
    for (int i = 0; i < 4; ++i) {
        int m = m0 + ty * 4 + i;
        float4 o;
        o.x = fmaxf(acc[i][0] + bv[0], 0.0f);
        o.y = fmaxf(acc[i][1] + bv[1], 0.0f);
        o.z = fmaxf(acc[i][2] + bv[2], 0.0f);
        o.w = fmaxf(acc[i][3] + bv[3], 0.0f);
        *(float4*)&out[(size_t)m * N1 + n0 + tx * 4] = o;
    }
}

// ---------------------------------------------------------------------------
extern "C" void kernel_launch(void* const* d_in, const int* in_sizes, int n_in,
                              void* d_out, int out_size)
{
    const float* inp1 = (const float*)d_in[0];   // [2048, 256]
    const float* inp2 = (const float*)d_in[1];   // [2048, 256]
    const float* W1   = (const float*)d_in[2];   // [66049, 512]
    const float* b1   = (const float*)d_in[3];   // [512]
    const float* W2   = (const float*)d_in[4];   // [512, 512]
    const float* b2   = (const float*)d_in[5];   // [512]
    (void)in_sizes; (void)n_in; (void)out_size;

    const size_t smem = (size_t)(BM * CSTR + 3 * G_I * WK * WSTR) * sizeof(float); // 206,848 B
    cudaFuncSetAttribute(fused_k1, cudaFuncAttributeMaxDynamicSharedMemorySize, (int)smem);

    fused_k1<<<dim3(N1 / BN, B_SZ / BM), 256, smem>>>(inp1, inp2, W1, b1);
    fused_k2<<<dim3(N1 / 64, B_SZ / 64), 256>>>(W2, b2, (float*)d_out);
}

// round 4
// speedup vs baseline: 1.3483x; 1.3483x over previous
#include <cuda_runtime.h>
#include <cuda_fp16.h>
#include <cstdint>
#include <cstddef>

// ---------------- problem constants ----------------
#define B_SZ   2048
#define I_SZ   256
#define P_SZ   257
#define FLATK  66049        // 257*257
#define N1     512

// ---------------- kernel-1 tiling ----------------
#define BM     128
#define BN     64
#define PJ     288          // padded j extent (9 tiles * 32)
#define CSTR   296          // c_s row stride in halves
#define KSTR   38           // B tile k stride in halves (conflict-free LDS+STS)
#define NKT    9            // j tiles per i
#define NIG    129          // ceil(257/2) i-groups (i=2*ig+g, pad a=0 at i=257)
#define BS_HALVES (2*64*KSTR)   // one B buffer: 2 i's x 64 n x 38 k halves
#define SMEM_C_BYTES (BM*CSTR*2)            // 75776
#define SMEM_TOTAL   (SMEM_C_BYTES + 2*BS_HALVES*2)  // 95232

// intermediate H = relu(fusion@W1 + b1)
__device__ float g_H[(size_t)B_SZ * N1];

__device__ __forceinline__ void mma16(float* d, uint32_t a0, uint32_t a1,
                                      uint32_t a2, uint32_t a3,
                                      uint32_t b0, uint32_t b1) {
    asm volatile(
        "mma.sync.aligned.m16n8k16.row.col.f32.f16.f16.f32 "
        "{%0,%1,%2,%3}, {%4,%5,%6,%7}, {%8,%9}, {%0,%1,%2,%3};"
        : "+f"(d[0]), "+f"(d[1]), "+f"(d[2]), "+f"(d[3])
        : "r"(a0), "r"(a1), "r"(a2), "r"(a3), "r"(b0), "r"(b1));
}

// ---------------------------------------------------------------------------
// Kernel 1: H = relu( (a kr c) @ W1 + b1 )
//   h[m,n] = sum_i a[m,i] * ( sum_j c[m,j] * W1[i*257+j, n] )
// 256 threads = 8 warps (4 m-warps x 2 n-warps), warp tile 32x32,
// fp16 m16n8k16 mma, fp32 accum, a-scale applied in fp32 per i-group.
// ---------------------------------------------------------------------------
extern __shared__ char smem1[];

__global__ void __launch_bounds__(256, 1)
fused_k1(const float* __restrict__ inp1, const float* __restrict__ inp2,
         const float* __restrict__ W1, const float* __restrict__ b1)
{
    __half* c_s = (__half*)smem1;                       // [BM][CSTR] fp16
    __half* b_s = (__half*)(smem1 + SMEM_C_BYTES);      // [2][BS_HALVES]

    const int tid  = threadIdx.x;
    const int lane = tid & 31;
    const int wid  = tid >> 5;
    const int wm   = wid & 3;          // m-warp 0..3
    const int wn   = wid >> 2;         // n-warp 0..1
    const int gq   = lane >> 2;        // group-of-4 id (fragment row)
    const int tig  = lane & 3;         // thread-in-group (fragment col pair)
    const int m0   = blockIdx.y * BM;
    const int n0   = blockIdx.x * BN;

    // ---- stage c tile as fp16 (ones at j=256, zeros to 287) ----
    for (int idx = tid; idx < BM * PJ; idx += 256) {
        int m = idx / PJ, j = idx - m * PJ;
        float v = (j < I_SZ) ? inp2[(size_t)(m0 + m) * I_SZ + j]
                             : (j == I_SZ ? 1.0f : 0.0f);
        c_s[m * CSTR + j] = __float2half_rn(v);
    }

    // ---- W register-staging: 16 floats per thread per stage ----
    const int n_t = tid & 63;          // n column this thread loads
    const int kq  = tid >> 6;          // 0..3: k-subrange kq*8..kq*8+7
    float wreg[16];

    auto loadW = [&](int ig, int kt) {
        #pragma unroll
        for (int g = 0; g < 2; ++g) {
            int i = ig * 2 + g;
            #pragma unroll
            for (int e = 0; e < 8; ++e) {
                int row = i * P_SZ + kt * 32 + kq * 8 + e;
                if (row > FLATK - 1) row = FLATK - 1;   // A=0 covers pads
                wreg[g * 8 + e] = __ldg(&W1[(size_t)row * N1 + n0 + n_t]);
            }
        }
    };
    loadW(0, 0);

    float h_acc[2][4][4];
    #pragma unroll
    for (int mt = 0; mt < 2; ++mt)
        #pragma unroll
        for (int nt = 0; nt < 4; ++nt)
            #pragma unroll
            for (int r = 0; r < 4; ++r) h_acc[mt][nt][r] = 0.0f;

    __syncthreads();   // c_s ready

    int buf = 0;
    for (int ig = 0; ig < NIG; ++ig) {
        // a-scales for this i-group (exact fp32)
        float av[2][4];
        #pragma unroll
        for (int g = 0; g < 2; ++g) {
            int i = ig * 2 + g;
            #pragma unroll
            for (int r = 0; r < 4; ++r) {
                int m = m0 + wm * 32 + (r >> 1) * 16 + (r & 1) * 8 + gq;
                av[g][r] = (i < I_SZ) ? __ldg(&inp1[(size_t)m * I_SZ + i])
                                      : (i == I_SZ ? 1.0f : 0.0f);
            }
        }

        float tmp[2][2][4][4];
        #pragma unroll
        for (int g = 0; g < 2; ++g)
            #pragma unroll
            for (int mt = 0; mt < 2; ++mt)
                #pragma unroll
                for (int nt = 0; nt < 4; ++nt)
                    #pragma unroll
                    for (int r = 0; r < 4; ++r) tmp[g][mt][nt][r] = 0.0f;

        for (int kt = 0; kt < NKT; ++kt) {
            // ---- STS current W regs into Bs[buf] as fp16 [g][n][k] ----
            __half* bb = b_s + buf * BS_HALVES;
            #pragma unroll
            for (int g = 0; g < 2; ++g) {
                int base = (g * 64 + n_t) * KSTR + kq * 8;
                #pragma unroll
                for (int e = 0; e < 8; e += 2) {
                    __half2 h = __floats2half2_rn(wreg[g * 8 + e], wreg[g * 8 + e + 1]);
                    *(__half2*)&bb[base + e] = h;
                }
            }

            // ---- prefetch next stage W into regs ----
            int ktn = kt + 1, ign = ig;
            if (ktn == NKT) { ktn = 0; ++ign; }
            if (ign < NIG) loadW(ign, ktn);

            __syncthreads();   // Bs[buf] visible; prior-stage reads done

            // ---- A fragments from c_s (shared by both g's) ----
            const int j0 = kt * 32;
            uint32_t A[2][2][4];    // [ks][mt][reg]
            #pragma unroll
            for (int ks = 0; ks < 2; ++ks)
                #pragma unroll
                for (int mt = 0; mt < 2; ++mt) {
                    int row = wm * 32 + mt * 16 + gq;
                    int col = j0 + ks * 16 + tig * 2;
                    A[ks][mt][0] = *(const uint32_t*)&c_s[row * CSTR + col];
                    A[ks][mt][1] = *(const uint32_t*)&c_s[(row + 8) * CSTR + col];
                    A[ks][mt][2] = *(const uint32_t*)&c_s[row * CSTR + col + 8];
                    A[ks][mt][3] = *(const uint32_t*)&c_s[(row + 8) * CSTR + col + 8];
                }

            // ---- B fragments + MMAs ----
            #pragma unroll
            for (int g = 0; g < 2; ++g) {
                const __half* bg = bb + g * 64 * KSTR;
                #pragma unroll
                for (int ks = 0; ks < 2; ++ks) {
                    #pragma unroll
                    for (int nt = 0; nt < 4; ++nt) {
                        int ncol = wn * 32 + nt * 8 + gq;
                        int kk   = ks * 16 + tig * 2;
                        uint32_t b0 = *(const uint32_t*)&bg[ncol * KSTR + kk];
                        uint32_t b1 = *(const uint32_t*)&bg[ncol * KSTR + kk + 8];
                        #pragma unroll
                        for (int mt = 0; mt < 2; ++mt)
                            mma16(tmp[g][mt][nt],
                                  A[ks][mt][0], A[ks][mt][1], A[ks][mt][2], A[ks][mt][3],
                                  b0, b1);
                    }
                }
            }
            buf ^= 1;
        }

        // ---- scale by a[m,i] (fp32) and accumulate ----
        #pragma unroll
        for (int g = 0; g < 2; ++g)
            #pragma unroll
            for (int mt = 0; mt < 2; ++mt)
                #pragma unroll
                for (int nt = 0; nt < 4; ++nt)
                    #pragma unroll
                    for (int r = 0; r < 4; ++r)
                        h_acc[mt][nt][r] += av[g][mt * 2 + (r >> 1)] * tmp[g][mt][nt][r];
    }

    // ---- epilogue: + b1, relu, write H ----
    #pragma unroll
    for (int mt = 0; mt < 2; ++mt)
        #pragma unroll
        for (int nt = 0; nt < 4; ++nt) {
            int n_base = n0 + wn * 32 + nt * 8 + tig * 2;
            float bv0 = b1[n_base], bv1 = b1[n_base + 1];
            #pragma unroll
            for (int h = 0; h < 2; ++h) {
                int m = m0 + wm * 32 + mt * 16 + h * 8 + gq;
                float v0 = fmaxf(h_acc[mt][nt][h * 2 + 0] + bv0, 0.0f);
                float v1 = fmaxf(h_acc[mt][nt][h * 2 + 1] + bv1, 0.0f);
                *(float2*)&g_H[(size_t)m * N1 + n_base] = make_float2(v0, v1);
            }
        }
}

// ---------------------------------------------------------------------------
// Kernel 2: out = relu( H @ W2 + b2 )   (exact fp32 SIMT)
// ---------------------------------------------------------------------------
__global__ void __launch_bounds__(256)
fused_k2(const float* __restrict__ W2, const float* __restrict__ b2,
         float* __restrict__ out)
{
    __shared__ float As[16][68];
    __shared__ float Bs[16][68];

    const int tid = threadIdx.x;
    const int tx = tid & 15, ty = tid >> 4;
    const int m0 = blockIdx.y * 64, n0 = blockIdx.x * 64;

    float acc[4][4];
    #pragma unroll
    for (int i = 0; i < 4; ++i)
        #pragma unroll
        for (int j = 0; j < 4; ++j) acc[i][j] = 0.0f;

    for (int k0 = 0; k0 < N1; k0 += 16) {
        int am = tid >> 2, akq = tid & 3;
        float4 va = *(const float4*)&g_H[(size_t)(m0 + am) * N1 + k0 + akq * 4];
        int bk = tid >> 4, bng = tid & 15;
        float4 vb = *(const float4*)&W2[(size_t)(k0 + bk) * N1 + n0 + bng * 4];
        __syncthreads();
        As[akq * 4 + 0][am] = va.x;
        As[akq * 4 + 1][am] = va.y;
        As[akq * 4 + 2][am] = va.z;
        As[akq * 4 + 3][am] = va.w;
        *(float4*)&Bs[bk][bng * 4] = vb;
        __syncthreads();
        #pragma unroll
        for (int kk = 0; kk < 16; ++kk) {
            float4 a = *(const float4*)&As[kk][ty * 4];
            float4 b = *(const float4*)&Bs[kk][tx * 4];
            float aa[4] = {a.x, a.y, a.z, a.w};
            float bb[4] = {b.x, b.y, b.z, b.w};
            #pragma unroll
            for (int i = 0; i < 4; ++i)
                #pragma unroll
                for (int j = 0; j < 4; ++j) acc[i][j] += aa[i] * bb[j];
        }
    }

    float bv[4];
    #pragma unroll
    for (int j = 0; j < 4; ++j) bv[j] = b2[n0 + tx * 4 + j];
    #pragma unroll
    for (int i = 0; i < 4; ++i) {
        int m = m0 + ty * 4 + i;
        float4 o;
        o.x = fmaxf(acc[i][0] + bv[0], 0.0f);
        o.y = fmaxf(acc[i][1] + bv[1], 0.0f);
        o.z = fmaxf(acc[i][2] + bv[2], 0.0f);
        o.w = fmaxf(acc[i][3] + bv[3], 0.0f);
        *(float4*)&out[(size_t)m * N1 + n0 + tx * 4] = o;
    }
}

// ---------------------------------------------------------------------------
extern "C" void kernel_launch(void* const* d_in, const int* in_sizes, int n_in,
                              void* d_out, int out_size)
{
    const float* inp1 = (const float*)d_in[0];   // [2048, 256]
    const float* inp2 = (const float*)d_in[1];   // [2048, 256]
    const float* W1   = (const float*)d_in[2];   // [66049, 512]
    const float* b1   = (const float*)d_in[3];   // [512]
    const float* W2   = (const float*)d_in[4];   // [512, 512]
    const float* b2   = (const float*)d_in[5];   // [512]
    (void)in_sizes; (void)n_in; (void)out_size;

    cudaFuncSetAttribute(fused_k1, cudaFuncAttributeMaxDynamicSharedMemorySize, SMEM_TOTAL);

    fused_k1<<<dim3(N1 / BN, B_SZ / BM), 256, SMEM_TOTAL>>>(inp1, inp2, W1, b1);
    fused_k2<<<dim3(N1 / 64, B_SZ / 64), 256>>>(W2, b2, (float*)d_out);
}

// round 6
// speedup vs baseline: 1.5583x; 1.1557x over previous
#include <cuda_runtime.h>
#include <cuda_fp16.h>
#include <cstdint>
#include <cstddef>

// ---------------- problem constants ----------------
#define B_SZ   2048
#define I_SZ   256
#define P_SZ   257
#define FLATK  66049        // 257*257
#define N1     512

// ---------------- kernel-1 tiling ----------------
#define BM     128
#define BN     64
#define PJ     288          // padded j extent (9 tiles * 32)
#define CSTR   296          // c_s row stride in halves (592B: conflict-free ldmatrix)
#define NSTR   72           // B tile n stride in halves (144B: conflict-free)
#define NKT    9            // j tiles per i
#define NIG    129          // ceil(257/2) i-groups (i=2*ig+g, pad a=0 at i=257)
#define BS_HALVES (64*NSTR)               // one B buffer: 64 k-rows x 72 n halves
#define SMEM_C_BYTES (BM*CSTR*2)          // 75776
#define SMEM_TOTAL   (SMEM_C_BYTES + 2*BS_HALVES*2)  // 94208

// intermediate H = relu(fusion@W1 + b1)
__device__ float g_H[(size_t)B_SZ * N1];

__device__ __forceinline__ void mma16(float* d, uint32_t a0, uint32_t a1,
                                      uint32_t a2, uint32_t a3,
                                      uint32_t b0, uint32_t b1) {
    asm volatile(
        "mma.sync.aligned.m16n8k16.row.col.f32.f16.f16.f32 "
        "{%0,%1,%2,%3}, {%4,%5,%6,%7}, {%8,%9}, {%0,%1,%2,%3};"
        : "+f"(d[0]), "+f"(d[1]), "+f"(d[2]), "+f"(d[3])
        : "r"(a0), "r"(a1), "r"(a2), "r"(a3), "r"(b0), "r"(b1));
}

__device__ __forceinline__ uint32_t smem_u32(const void* p) {
    uint32_t a;
    asm("{ .reg .u64 t; cvta.to.shared.u64 t, %1; cvt.u32.u64 %0, t; }" : "=r"(a) : "l"(p));
    return a;
}
__device__ __forceinline__ void ldm_x4(uint32_t& r0, uint32_t& r1, uint32_t& r2,
                                       uint32_t& r3, uint32_t a) {
    asm volatile("ldmatrix.sync.aligned.m8n8.x4.shared.b16 {%0,%1,%2,%3}, [%4];"
                 : "=r"(r0), "=r"(r1), "=r"(r2), "=r"(r3) : "r"(a));
}
__device__ __forceinline__ void ldm_x4t(uint32_t& r0, uint32_t& r1, uint32_t& r2,
                                        uint32_t& r3, uint32_t a) {
    asm volatile("ldmatrix.sync.aligned.m8n8.x4.trans.shared.b16 {%0,%1,%2,%3}, [%4];"
                 : "=r"(r0), "=r"(r1), "=r"(r2), "=r"(r3) : "r"(a));
}

// ---------------------------------------------------------------------------
// Kernel 1: H = relu( (a kr c) @ W1 + b1 )
//   h[m,n] = sum_i a[m,i] * ( sum_j c[m,j] * W1[i*257+j, n] )
// 256 threads = 8 warps (4 m-warps x 2 n-warps), warp tile 32x32,
// fp16 m16n8k16 mma via ldmatrix, fp32 accum, a-scale in fp32 per i-group.
// ---------------------------------------------------------------------------
extern __shared__ char smem1[];

__global__ void __launch_bounds__(256, 1)
fused_k1(const float* __restrict__ inp1, const float* __restrict__ inp2,
         const float* __restrict__ W1, const float* __restrict__ b1)
{
    __half* c_s = (__half*)smem1;                       // [BM][CSTR] fp16
    __half* b_s = (__half*)(smem1 + SMEM_C_BYTES);      // [2][64][NSTR] fp16

    const int tid  = threadIdx.x;
    const int lane = tid & 31;
    const int wid  = tid >> 5;
    const int wm   = wid & 3;          // m-warp 0..3
    const int wn   = wid >> 2;         // n-warp 0..1
    const int gq   = lane >> 2;        // fragment row
    const int tig  = lane & 3;         // fragment col pair
    const int m0   = blockIdx.y * BM;
    const int n0   = blockIdx.x * BN;

    const uint32_t c_base  = smem_u32(c_s);
    const uint32_t b_base  = smem_u32(b_s);

    // ldmatrix lane->address decomposition (shared by A and B)
    const int quad = lane >> 3, lrow = lane & 7;
    const int lmr  = (quad & 1) * 8 + lrow;   // row within 16
    const int lmc  = (quad >> 1) * 8;         // col offset (0 or 8)

    // ---- stage c tile as fp16 (ones at j=256, zeros to 287) ----
    for (int idx = tid; idx < BM * PJ; idx += 256) {
        int m = idx / PJ, j = idx - m * PJ;
        float v = (j < I_SZ) ? inp2[(size_t)(m0 + m) * I_SZ + j]
                             : (j == I_SZ ? 1.0f : 0.0f);
        c_s[m * CSTR + j] = __float2half_rn(v);
    }

    // ---- W register staging: 4x LDG.128 per thread per stage ----
    const int nv  = (tid & 15) * 4;    // n offset (float4)
    const int rr0 = tid >> 4;          // base row 0..15 (rows rr0 + 16p)
    float4 wreg[4];

    auto loadW = [&](int ig, int kt) {
        #pragma unroll
        for (int p = 0; p < 4; ++p) {
            int row = rr0 + p * 16;              // 0..63
            int i   = ig * 2 + (row >> 5);
            int grow = i * P_SZ + kt * 32 + (row & 31);
            if (grow > FLATK - 1) grow = FLATK - 1;   // A=0 covers pads
            wreg[p] = *(const float4*)&W1[(size_t)grow * N1 + n0 + nv];
        }
    };
    loadW(0, 0);

    float h_acc[2][4][4];
    #pragma unroll
    for (int mt = 0; mt < 2; ++mt)
        #pragma unroll
        for (int nt = 0; nt < 4; ++nt)
            #pragma unroll
            for (int r = 0; r < 4; ++r) h_acc[mt][nt][r] = 0.0f;

    __syncthreads();   // c_s ready

    int buf = 0;
    for (int ig = 0; ig < NIG; ++ig) {
        // a-scales for this i-group (exact fp32)
        float av[2][4];
        #pragma unroll
        for (int g = 0; g < 2; ++g) {
            int i = ig * 2 + g;
            #pragma unroll
            for (int r = 0; r < 4; ++r) {
                int m = m0 + wm * 32 + (r >> 1) * 16 + (r & 1) * 8 + gq;
                av[g][r] = (i < I_SZ) ? __ldg(&inp1[(size_t)m * I_SZ + i])
                                      : (i == I_SZ ? 1.0f : 0.0f);
            }
        }

        float tmp[2][2][4][4];
        #pragma unroll
        for (int g = 0; g < 2; ++g)
            #pragma unroll
            for (int mt = 0; mt < 2; ++mt)
                #pragma unroll
                for (int nt = 0; nt < 4; ++nt)
                    #pragma unroll
                    for (int r = 0; r < 4; ++r) tmp[g][mt][nt][r] = 0.0f;

        for (int kt = 0; kt < NKT; ++kt) {
            // ---- STS current W regs into b_s[buf] as [k][n] fp16 ----
            __half* bb = b_s + buf * BS_HALVES;
            #pragma unroll
            for (int p = 0; p < 4; ++p) {
                int row = rr0 + p * 16;          // k-row 0..63 (g*32 + klocal)
                __half2 h0 = __floats2half2_rn(wreg[p].x, wreg[p].y);
                __half2 h1 = __floats2half2_rn(wreg[p].z, wreg[p].w);
                uint2 v;
                v.x = *(uint32_t*)&h0;
                v.y = *(uint32_t*)&h1;
                *(uint2*)&bb[row * NSTR + nv] = v;
            }

            // ---- prefetch next stage W into regs ----
            int ktn = kt + 1, ign = ig;
            if (ktn == NKT) { ktn = 0; ++ign; }
            if (ign < NIG) loadW(ign, ktn);

            __syncthreads();   // b_s[buf] visible; prior reads of this buf done

            // ---- A fragments via ldmatrix (shared by both g's) ----
            const int j0 = kt * 32;
            uint32_t A[2][2][4];    // [ks][mt][reg]
            #pragma unroll
            for (int ks = 0; ks < 2; ++ks)
                #pragma unroll
                for (int mt = 0; mt < 2; ++mt) {
                    uint32_t addr = c_base + 2u * (uint32_t)(
                        (wm * 32 + mt * 16 + lmr) * CSTR + j0 + ks * 16 + lmc);
                    ldm_x4(A[ks][mt][0], A[ks][mt][1], A[ks][mt][2], A[ks][mt][3], addr);
                }

            // ---- B fragments via ldmatrix.trans + MMAs ----
            const uint32_t bbase_u = b_base + (uint32_t)(buf * BS_HALVES * 2);
            #pragma unroll
            for (int g = 0; g < 2; ++g) {
                #pragma unroll
                for (int ks = 0; ks < 2; ++ks) {
                    #pragma unroll
                    for (int nh = 0; nh < 2; ++nh) {
                        uint32_t addr = bbase_u + 2u * (uint32_t)(
                            (g * 32 + ks * 16 + lmr) * NSTR + wn * 32 + nh * 16 + lmc);
                        uint32_t b0, b1, b2, b3;
                        ldm_x4t(b0, b1, b2, b3, addr);
                        #pragma unroll
                        for (int mt = 0; mt < 2; ++mt) {
                            mma16(tmp[g][mt][nh * 2 + 0],
                                  A[ks][mt][0], A[ks][mt][1], A[ks][mt][2], A[ks][mt][3],
                                  b0, b1);
                            mma16(tmp[g][mt][nh * 2 + 1],
                                  A[ks][mt][0], A[ks][mt][1], A[ks][mt][2], A[ks][mt][3],
                                  b2, b3);
                        }
                    }
                }
            }
            buf ^= 1;
        }

        // ---- scale by a[m,i] (fp32) and accumulate ----
        #pragma unroll
        for (int g = 0; g < 2; ++g)
            #pragma unroll
            for (int mt = 0; mt < 2; ++mt)
                #pragma unroll
                for (int nt = 0; nt < 4; ++nt)
                    #pragma unroll
                    for (int r = 0; r < 4; ++r)
                        h_acc[mt][nt][r] += av[g][mt * 2 + (r >> 1)] * tmp[g][mt][nt][r];
    }

    // ---- epilogue: + b1, relu, write H ----
    #pragma unroll
    for (int mt = 0; mt < 2; ++mt)
        #pragma unroll
        for (int nt = 0; nt < 4; ++nt) {
            int n_base = n0 + wn * 32 + nt * 8 + tig * 2;
            float bv0 = b1[n_base], bv1 = b1[n_base + 1];
            #pragma unroll
            for (int h = 0; h < 2; ++h) {
                int m = m0 + wm * 32 + mt * 16 + h * 8 + gq;
                float v0 = fmaxf(h_acc[mt][nt][h * 2 + 0] + bv0, 0.0f);
                float v1 = fmaxf(h_acc[mt][nt][h * 2 + 1] + bv1, 0.0f);
                *(float2*)&g_H[(size_t)m * N1 + n_base] = make_float2(v0, v1);
            }
        }
}

// ---------------------------------------------------------------------------
// Kernel 2: out = relu( H @ W2 + b2 )   (exact fp32 SIMT)
// ---------------------------------------------------------------------------
__global__ void __launch_bounds__(256)
fused_k2(const float* __restrict__ W2, const float* __restrict__ b2,
         float* __restrict__ out)
{
    __shared__ float As[16][68];
    __shared__ float Bs[16][68];

    const int tid = threadIdx.x;
    const int tx = tid & 15, ty = tid >> 4;
    const int m0 = blockIdx.y * 64, n0 = blockIdx.x * 64;

    float acc[4][4];
    #pragma unroll
    for (int i = 0; i < 4; ++i)
        #pragma unroll
        for (int j = 0; j < 4; ++j) acc[i][j] = 0.0f;

    for (int k0 = 0; k0 < N1; k0 += 16) {
        int am = tid >> 2, akq = tid & 3;
        float4 va = *(const float4*)&g_H[(size_t)(m0 + am) * N1 + k0 + akq * 4];
        int bk = tid >> 4, bng = tid & 15;
        float4 vb = *(const float4*)&W2[(size_t)(k0 + bk) * N1 + n0 + bng * 4];
        __syncthreads();
        As[akq * 4 + 0][am] = va.x;
        As[akq * 4 + 1][am] = va.y;
        As[akq * 4 + 2][am] = va.z;
        As[akq * 4 + 3][am] = va.w;
        *(float4*)&Bs[bk][bng * 4] = vb;
        __syncthreads();
        #pragma unroll
        for (int kk = 0; kk < 16; ++kk) {
            float4 a = *(const float4*)&As[kk][ty * 4];
            float4 b = *(const float4*)&Bs[kk][tx * 4];
            float aa[4] = {a.x, a.y, a.z, a.w};
            float bb[4] = {b.x, b.y, b.z, b.w};
            #pragma unroll
            for (int i = 0; i < 4; ++i)
                #pragma unroll
                for (int j = 0; j < 4; ++j) acc[i][j] += aa[i] * bb[j];
        }
    }

    float bv[4];
    #pragma unroll
    for (int j = 0; j < 4; ++j) bv[j] = b2[n0 + tx * 4 + j];
    #pragma unroll
    for (int i = 0; i < 4; ++i) {
        int m = m0 + ty * 4 + i;
        float4 o;
        o.x = fmaxf(acc[i][0] + bv[0], 0.0f);
        o.y = fmaxf(acc[i][1] + bv[1], 0.0f);
        o.z = fmaxf(acc[i][2] + bv[2], 0.0f);
        o.w = fmaxf(acc[i][3] + bv[3], 0.0f);
        *(float4*)&out[(size_t)m * N1 + n0 + tx * 4] = o;
    }
}

// ---------------------------------------------------------------------------
extern "C" void kernel_launch(void* const* d_in, const int* in_sizes, int n_in,
                              void* d_out, int out_size)
{
    const float* inp1 = (const float*)d_in[0];   // [2048, 256]
    const float* inp2 = (const float*)d_in[1];   // [2048, 256]
    const float* W1   = (const float*)d_in[2];   // [66049, 512]
    const float* b1   = (const float*)d_in[3];   // [512]
    const float* W2   = (const float*)d_in[4];   // [512, 512]
    const float* b2   = (const float*)d_in[5];   // [512]
    (void)in_sizes; (void)n_in; (void)out_size;

    cudaFuncSetAttribute(fused_k1, cudaFuncAttributeMaxDynamicSharedMemorySize, SMEM_TOTAL);

    fused_k1<<<dim3(N1 / BN, B_SZ / BM), 256, SMEM_TOTAL>>>(inp1, inp2, W1, b1);
    fused_k2<<<dim3(N1 / 64, B_SZ / 64), 256>>>(W2, b2, (float*)d_out);
}

// round 8
// speedup vs baseline: 2.1402x; 1.3735x over previous
#include <cuda_runtime.h>
#include <cuda_fp16.h>
#include <cstdint>
#include <cstddef>

// ---------------- problem constants ----------------
#define B_SZ   2048
#define I_SZ   256
#define P_SZ   257
#define FLATK  66049        // 257*257
#define N1     512

// ---------------- kernel-1 tiling ----------------
#define BM     128
#define BN     64
#define PJ     288          // padded j extent (9 tiles * 32)
#define CSTR   296          // c_s row stride in halves (conflict-free ldmatrix)
#define NSTR   72           // B tile n stride in halves (144B rows, conflict-free)
#define NKT    9            // j tiles per i
#define BS_HALVES (64*NSTR)               // one B buffer: 64 k-rows x 72 n halves (9216 B)
#define SMEM_C_BYTES (BM*CSTR*2)          // 75776
#define SMEM_TOTAL   (SMEM_C_BYTES + 6*BS_HALVES*2)  // 75776 + 55296 = 131072

// statics: fp16 W1 + intermediate H
__device__ __half g_W1h[(size_t)FLATK * N1];     // 67.6 MB
__device__ float  g_H[(size_t)B_SZ * N1];        // 4 MB

__device__ __forceinline__ void mma16(float* d, uint32_t a0, uint32_t a1,
                                      uint32_t a2, uint32_t a3,
                                      uint32_t b0, uint32_t b1) {
    asm volatile(
        "mma.sync.aligned.m16n8k16.row.col.f32.f16.f16.f32 "
        "{%0,%1,%2,%3}, {%4,%5,%6,%7}, {%8,%9}, {%0,%1,%2,%3};"
        : "+f"(d[0]), "+f"(d[1]), "+f"(d[2]), "+f"(d[3])
        : "r"(a0), "r"(a1), "r"(a2), "r"(a3), "r"(b0), "r"(b1));
}
__device__ __forceinline__ uint32_t smem_u32(const void* p) {
    uint32_t a;
    asm("{ .reg .u64 t; cvta.to.shared.u64 t, %1; cvt.u32.u64 %0, t; }" : "=r"(a) : "l"(p));
    return a;
}
__device__ __forceinline__ void ldm_x4(uint32_t& r0, uint32_t& r1, uint32_t& r2,
                                       uint32_t& r3, uint32_t a) {
    asm volatile("ldmatrix.sync.aligned.m8n8.x4.shared.b16 {%0,%1,%2,%3}, [%4];"
                 : "=r"(r0), "=r"(r1), "=r"(r2), "=r"(r3) : "r"(a));
}
__device__ __forceinline__ void ldm_x4t(uint32_t& r0, uint32_t& r1, uint32_t& r2,
                                        uint32_t& r3, uint32_t a) {
    asm volatile("ldmatrix.sync.aligned.m8n8.x4.trans.shared.b16 {%0,%1,%2,%3}, [%4];"
                 : "=r"(r0), "=r"(r1), "=r"(r2), "=r"(r3) : "r"(a));
}
__device__ __forceinline__ void cpa16(uint32_t s, const void* g) {
    asm volatile("cp.async.cg.shared.global [%0], [%1], 16;" :: "r"(s), "l"(g));
}
__device__ __forceinline__ void cpcommit() { asm volatile("cp.async.commit_group;"); }
__device__ __forceinline__ void cpwait1()  { asm volatile("cp.async.wait_group 1;"); }
__device__ __forceinline__ void bar_named(int id) {
    asm volatile("bar.sync %0, 256;" :: "r"(id) : "memory");
}

// ---------------------------------------------------------------------------
// Kernel 0: convert W1 -> fp16 (once per launch).
// total elements = 66049*512 = 33,817,088 (divisible by 8, NOT by 2048*8).
// ---------------------------------------------------------------------------
__global__ void __launch_bounds__(256)
convW(const float* __restrict__ W1)
{
    const size_t total = (size_t)FLATK * N1;
    size_t idx = ((size_t)blockIdx.x * 256 + threadIdx.x) * 8;
    if (idx >= total) return;          // tail guard (total % 8 == 0)
    float4 v0 = *(const float4*)(W1 + idx);
    float4 v1 = *(const float4*)(W1 + idx + 4);
    __half2 h0 = __floats2half2_rn(v0.x, v0.y);
    __half2 h1 = __floats2half2_rn(v0.z, v0.w);
    __half2 h2 = __floats2half2_rn(v1.x, v1.y);
    __half2 h3 = __floats2half2_rn(v1.z, v1.w);
    uint4 u;
    u.x = *(uint32_t*)&h0; u.y = *(uint32_t*)&h1;
    u.z = *(uint32_t*)&h2; u.w = *(uint32_t*)&h3;
    *(uint4*)(g_W1h + idx) = u;
}

// ---------------------------------------------------------------------------
// Kernel 1: H = relu( (a kr c) @ W1 + b1 )
// 512 threads = 2 warp-groups of 8 warps; group g handles half the i-range.
// Each group: triple-buffered cp.async fp16 W ring + own named barrier.
// Warp tile 32x32 fp16 m16n8k16, fp32 accum, fp32 a-scale per i-group.
// ---------------------------------------------------------------------------
extern __shared__ char smem1[];

__global__ void __launch_bounds__(512, 1)
fused_k1(const float* __restrict__ inp1, const float* __restrict__ inp2,
         const float* __restrict__ b1)
{
    __half* c_s = (__half*)smem1;                       // [BM][CSTR]
    __half* b_s = (__half*)(smem1 + SMEM_C_BYTES);      // [2 grp][3][BS_HALVES]

    const int tid  = threadIdx.x;
    const int lane = tid & 31;
    const int wid  = tid >> 5;
    const int grp  = wid >> 3;         // warp-group 0/1
    const int gtid = tid & 255;
    const int gwid = wid & 7;
    const int wm   = gwid & 3;         // m-warp 0..3
    const int wn   = gwid >> 2;        // n-warp 0..1
    const int gq   = lane >> 2;
    const int tig  = lane & 3;
    const int m0   = blockIdx.y * BM;
    const int n0   = blockIdx.x * BN;

    const int igbase = grp ? 65 : 0;
    const int nig_g  = grp ? 64 : 65;

    const uint32_t c_base  = smem_u32(c_s);
    const uint32_t bring_u = smem_u32(b_s) + (uint32_t)(grp * 3 * BS_HALVES * 2);

    // ldmatrix lane decomposition
    const int quad = lane >> 3, lrow = lane & 7;
    const int lmr  = (quad & 1) * 8 + lrow;
    const int lmc  = (quad >> 1) * 8;

    // ---- stage c tile as fp16 (ones at j=256, zeros to 287) ----
    for (int idx = tid; idx < BM * PJ; idx += 512) {
        int m = idx / PJ, j = idx - m * PJ;
        float v = (j < I_SZ) ? inp2[(size_t)(m0 + m) * I_SZ + j]
                             : (j == I_SZ ? 1.0f : 0.0f);
        c_s[m * CSTR + j] = __float2half_rn(v);
    }
    __syncthreads();

    // ---- W stage loader: fp16 rows into [k][n] tile via cp.async ----
    auto issueW = [&](int igl, int kt, int buf) {
        int ig = igbase + igl;
        #pragma unroll
        for (int q = 0; q < 2; ++q) {
            int ch  = gtid + q * 256;        // 0..511 16B chunks
            int row = ch >> 3;               // k-row 0..63
            int c16 = ch & 7;
            int i   = ig * 2 + (row >> 5);
            int grow = i * P_SZ + kt * 32 + (row & 31);
            if (grow > FLATK - 1) grow = FLATK - 1;   // av=0 covers pads
            const __half* src = g_W1h + (size_t)grow * N1 + n0 + c16 * 8;
            uint32_t dst = bring_u + (uint32_t)(buf * BS_HALVES * 2 + row * 144 + c16 * 16);
            cpa16(dst, src);
        }
    };

    float h_acc[2][4][4];
    #pragma unroll
    for (int mt = 0; mt < 2; ++mt)
        #pragma unroll
        for (int nt = 0; nt < 4; ++nt)
            #pragma unroll
            for (int r = 0; r < 4; ++r) h_acc[mt][nt][r] = 0.0f;

    issueW(0, 0, 0); cpcommit();
    issueW(0, 1, 1); cpcommit();

    int bufR = 0, bufW = 2;

    for (int igl = 0; igl < nig_g; ++igl) {
        // a-scales for this i-group (exact fp32)
        float av[2][4];
        #pragma unroll
        for (int g = 0; g < 2; ++g) {
            int i = (igbase + igl) * 2 + g;
            #pragma unroll
            for (int q = 0; q < 4; ++q) {
                int m = m0 + wm * 32 + (q >> 1) * 16 + (q & 1) * 8 + gq;
                av[g][q] = (i < I_SZ) ? __ldg(&inp1[(size_t)m * I_SZ + i])
                                      : (i == I_SZ ? 1.0f : 0.0f);
            }
        }

        float tmp[2][2][4][4];
        #pragma unroll
        for (int g = 0; g < 2; ++g)
            #pragma unroll
            for (int mt = 0; mt < 2; ++mt)
                #pragma unroll
                for (int nt = 0; nt < 4; ++nt)
                    #pragma unroll
                    for (int q = 0; q < 4; ++q) tmp[g][mt][nt][q] = 0.0f;

        for (int kt = 0; kt < NKT; ++kt) {
            // ---- A fragments (c_s immutable: no barrier dependency) ----
            const int j0 = kt * 32;
            uint32_t A[2][2][4];
            #pragma unroll
            for (int ks = 0; ks < 2; ++ks)
                #pragma unroll
                for (int mt = 0; mt < 2; ++mt) {
                    uint32_t addr = c_base + 2u * (uint32_t)(
                        (wm * 32 + mt * 16 + lmr) * CSTR + j0 + ks * 16 + lmc);
                    ldm_x4(A[ks][mt][0], A[ks][mt][1], A[ks][mt][2], A[ks][mt][3], addr);
                }

            cpwait1();                 // this thread's stage-r data landed
            bar_named(grp + 1);        // group-wide: data visible, prior reads done

            // issue stage r+2
            int kt2 = kt + 2, ig2 = igl;
            if (kt2 >= NKT) { kt2 -= NKT; ++ig2; }
            if (ig2 < nig_g) issueW(ig2, kt2, bufW);
            cpcommit();

            // ---- B fragments + MMAs ----
            const uint32_t bb = bring_u + (uint32_t)(bufR * BS_HALVES * 2);
            #pragma unroll
            for (int g = 0; g < 2; ++g) {
                #pragma unroll
                for (int ks = 0; ks < 2; ++ks) {
                    #pragma unroll
                    for (int nh = 0; nh < 2; ++nh) {
                        uint32_t addr = bb + 2u * (uint32_t)(
                            (g * 32 + ks * 16 + lmr) * NSTR + wn * 32 + nh * 16 + lmc);
                        uint32_t b0, b1, b2, b3;
                        ldm_x4t(b0, b1, b2, b3, addr);
                        #pragma unroll
                        for (int mt = 0; mt < 2; ++mt) {
                            mma16(tmp[g][mt][nh * 2 + 0],
                                  A[ks][mt][0], A[ks][mt][1], A[ks][mt][2], A[ks][mt][3],
                                  b0, b1);
                            mma16(tmp[g][mt][nh * 2 + 1],
                                  A[ks][mt][0], A[ks][mt][1], A[ks][mt][2], A[ks][mt][3],
                                  b2, b3);
                        }
                    }
                }
            }
            bufR = (bufR == 2) ? 0 : bufR + 1;
            bufW = (bufW == 2) ? 0 : bufW + 1;
        }

        // ---- scale by a[m,i] (fp32) and accumulate ----
        #pragma unroll
        for (int g = 0; g < 2; ++g)
            #pragma unroll
            for (int mt = 0; mt < 2; ++mt)
                #pragma unroll
                for (int nt = 0; nt < 4; ++nt)
                    #pragma unroll
                    for (int q = 0; q < 4; ++q)
                        h_acc[mt][nt][q] += av[g][mt * 2 + (q >> 1)] * tmp[g][mt][nt][q];
    }

    // ---- cross-group reduce through retired c_s region ----
    __syncthreads();
    float* xbuf = (float*)smem1;   // 256*36*4 = 36864 B < 75776
    if (grp == 1) {
        #pragma unroll
        for (int mt = 0; mt < 2; ++mt)
            #pragma unroll
            for (int nt = 0; nt < 4; ++nt)
                *(float4*)&xbuf[gtid * 36 + (mt * 4 + nt) * 4] =
                    make_float4(h_acc[mt][nt][0], h_acc[mt][nt][1],
                                h_acc[mt][nt][2], h_acc[mt][nt][3]);
    }
    __syncthreads();
    if (grp == 0) {
        #pragma unroll
        for (int mt = 0; mt < 2; ++mt)
            #pragma unroll
            for (int nt = 0; nt < 4; ++nt) {
                float4 p = *(const float4*)&xbuf[gtid * 36 + (mt * 4 + nt) * 4];
                h_acc[mt][nt][0] += p.x; h_acc[mt][nt][1] += p.y;
                h_acc[mt][nt][2] += p.z; h_acc[mt][nt][3] += p.w;

                int n_base = n0 + wn * 32 + nt * 8 + tig * 2;
                float bv0 = b1[n_base], bv1 = b1[n_base + 1];
                #pragma unroll
                for (int h = 0; h < 2; ++h) {
                    int m = m0 + wm * 32 + mt * 16 + h * 8 + gq;
                    float v0 = fmaxf(h_acc[mt][nt][h * 2 + 0] + bv0, 0.0f);
                    float v1 = fmaxf(h_acc[mt][nt][h * 2 + 1] + bv1, 0.0f);
                    *(float2*)&g_H[(size_t)m * N1 + n_base] = make_float2(v0, v1);
                }
            }
    }
}

// ---------------------------------------------------------------------------
// Kernel 2: out = relu( H @ W2 + b2 )   (exact fp32 SIMT)
// ---------------------------------------------------------------------------
__global__ void __launch_bounds__(256)
fused_k2(const float* __restrict__ W2, const float* __restrict__ b2,
         float* __restrict__ out)
{
    __shared__ float As[16][68];
    __shared__ float Bs[16][68];

    const int tid = threadIdx.x;
    const int tx = tid & 15, ty = tid >> 4;
    const int m0 = blockIdx.y * 64, n0 = blockIdx.x * 64;

    float acc[4][4];
    #pragma unroll
    for (int i = 0; i < 4; ++i)
        #pragma unroll
        for (int j = 0; j < 4; ++j) acc[i][j] = 0.0f;

    for (int k0 = 0; k0 < N1; k0 += 16) {
        int am = tid >> 2, akq = tid & 3;
        float4 va = *(const float4*)&g_H[(size_t)(m0 + am) * N1 + k0 + akq * 4];
        int bk = tid >> 4, bng = tid & 15;
        float4 vb = *(const float4*)&W2[(size_t)(k0 + bk) * N1 + n0 + bng * 4];
        __syncthreads();
        As[akq * 4 + 0][am] = va.x;
        As[akq * 4 + 1][am] = va.y;
        As[akq * 4 + 2][am] = va.z;
        As[akq * 4 + 3][am] = va.w;
        *(float4*)&Bs[bk][bng * 4] = vb;
        __syncthreads();
        #pragma unroll
        for (int kk = 0; kk < 16; ++kk) {
            float4 a = *(const float4*)&As[kk][ty * 4];
            float4 b = *(const float4*)&Bs[kk][tx * 4];
            float aa[4] = {a.x, a.y, a.z, a.w};
            float bb[4] = {b.x, b.y, b.z, b.w};
            #pragma unroll
            for (int i = 0; i < 4; ++i)
                #pragma unroll
                for (int j = 0; j < 4; ++j) acc[i][j] += aa[i] * bb[j];
        }
    }

    float bv[4];
    #pragma unroll
    for (int j = 0; j < 4; ++j) bv[j] = b2[n0 + tx * 4 + j];
    #pragma unroll
    for (int i = 0; i < 4; ++i) {
        int m = m0 + ty * 4 + i;
        float4 o;
        o.x = fmaxf(acc[i][0] + bv[0], 0.0f);
        o.y = fmaxf(acc[i][1] + bv[1], 0.0f);
        o.z = fmaxf(acc[i][2] + bv[2], 0.0f);
        o.w = fmaxf(acc[i][3] + bv[3], 0.0f);
        *(float4*)&out[(size_t)m * N1 + n0 + tx * 4] = o;
    }
}

// ---------------------------------------------------------------------------
extern "C" void kernel_launch(void* const* d_in, const int* in_sizes, int n_in,
                              void* d_out, int out_size)
{
    const float* inp1 = (const float*)d_in[0];   // [2048, 256]
    const float* inp2 = (const float*)d_in[1];   // [2048, 256]
    const float* W1   = (const float*)d_in[2];   // [66049, 512]
    const float* b1   = (const float*)d_in[3];   // [512]
    const float* W2   = (const float*)d_in[4];   // [512, 512]
    const float* b2   = (const float*)d_in[5];   // [512]
    (void)in_sizes; (void)n_in; (void)out_size;

    // W1 -> fp16: ceil(66049*512 / (256*8)) = 16513 blocks (tail-guarded)
    convW<<<16513, 256>>>(W1);

    cudaFuncSetAttribute(fused_k1, cudaFuncAttributeMaxDynamicSharedMemorySize, SMEM_TOTAL);
    fused_k1<<<dim3(N1 / BN, B_SZ / BM), 512, SMEM_TOTAL>>>(inp1, inp2, b1);
    fused_k2<<<dim3(N1 / 64, B_SZ / 64), 256>>>(W2, b2, (float*)d_out);
}

// round 9
// speedup vs baseline: 2.2605x; 1.0562x over previous
#include <cuda_runtime.h>
#include <cuda_fp16.h>
#include <cstdint>
#include <cstddef>

// ---------------- problem constants ----------------
#define B_SZ   2048
#define I_SZ   256
#define P_SZ   257
#define FLATK  66049        // 257*257
#define N1     512

// ---------------- kernel-1 tiling ----------------
#define BM     128
#define BN     64
#define PJ     288          // padded j extent (9 tiles * 32)
#define CSTR   296          // c_s row stride in halves (conflict-free ldmatrix)
#define NSTR   72           // B tile n stride in halves (144B rows, conflict-free)
#define NKT    9            // j tiles per i
#define BS_HALVES (64*NSTR)               // one B buffer (9216 B)
#define SMEM_C_BYTES (BM*CSTR*2)          // 75776
#define SMEM_TOTAL   (SMEM_C_BYTES + 6*BS_HALVES*2)  // 131072

// ---------------- kernel-2 tiling ----------------
#define K2_BK    64
#define K2_ABUF  18432      // 128 rows * 72 halves * 2B
#define K2_BBUF  9216       // 64 rows * 72 halves * 2B
#define K2_BUF   (K2_ABUF + K2_BBUF)          // 27648
#define K2_SMEM  (3 * K2_BUF)                 // 82944

// statics: fp16 W1/W2 + fp16 intermediate H
__device__ __half g_W1h[(size_t)FLATK * N1];     // 67.6 MB
__device__ __half g_W2h[(size_t)N1 * N1];        // 0.5 MB
__device__ __half g_Hh[(size_t)B_SZ * N1];       // 2 MB

__device__ __forceinline__ void mma16(float* d, uint32_t a0, uint32_t a1,
                                      uint32_t a2, uint32_t a3,
                                      uint32_t b0, uint32_t b1) {
    asm volatile(
        "mma.sync.aligned.m16n8k16.row.col.f32.f16.f16.f32 "
        "{%0,%1,%2,%3}, {%4,%5,%6,%7}, {%8,%9}, {%0,%1,%2,%3};"
        : "+f"(d[0]), "+f"(d[1]), "+f"(d[2]), "+f"(d[3])
        : "r"(a0), "r"(a1), "r"(a2), "r"(a3), "r"(b0), "r"(b1));
}
__device__ __forceinline__ uint32_t smem_u32(const void* p) {
    uint32_t a;
    asm("{ .reg .u64 t; cvta.to.shared.u64 t, %1; cvt.u32.u64 %0, t; }" : "=r"(a) : "l"(p));
    return a;
}
__device__ __forceinline__ void ldm_x4(uint32_t& r0, uint32_t& r1, uint32_t& r2,
                                       uint32_t& r3, uint32_t a) {
    asm volatile("ldmatrix.sync.aligned.m8n8.x4.shared.b16 {%0,%1,%2,%3}, [%4];"
                 : "=r"(r0), "=r"(r1), "=r"(r2), "=r"(r3) : "r"(a));
}
__device__ __forceinline__ void ldm_x4t(uint32_t& r0, uint32_t& r1, uint32_t& r2,
                                        uint32_t& r3, uint32_t a) {
    asm volatile("ldmatrix.sync.aligned.m8n8.x4.trans.shared.b16 {%0,%1,%2,%3}, [%4];"
                 : "=r"(r0), "=r"(r1), "=r"(r2), "=r"(r3) : "r"(a));
}
__device__ __forceinline__ void cpa16(uint32_t s, const void* g) {
    asm volatile("cp.async.cg.shared.global [%0], [%1], 16;" :: "r"(s), "l"(g));
}
__device__ __forceinline__ void cpcommit() { asm volatile("cp.async.commit_group;"); }
__device__ __forceinline__ void cpwait1()  { asm volatile("cp.async.wait_group 1;"); }
__device__ __forceinline__ void bar_named(int id) {
    asm volatile("bar.sync %0, 256;" :: "r"(id) : "memory");
}

// ---------------------------------------------------------------------------
// Kernel 0a/0b: convert W1 / W2 -> fp16
// ---------------------------------------------------------------------------
__global__ void __launch_bounds__(256)
convW(const float* __restrict__ W1)
{
    const size_t total = (size_t)FLATK * N1;   // 33,817,088 (div by 8)
    size_t idx = ((size_t)blockIdx.x * 256 + threadIdx.x) * 8;
    if (idx >= total) return;
    float4 v0 = *(const float4*)(W1 + idx);
    float4 v1 = *(const float4*)(W1 + idx + 4);
    __half2 h0 = __floats2half2_rn(v0.x, v0.y);
    __half2 h1 = __floats2half2_rn(v0.z, v0.w);
    __half2 h2 = __floats2half2_rn(v1.x, v1.y);
    __half2 h3 = __floats2half2_rn(v1.z, v1.w);
    uint4 u;
    u.x = *(uint32_t*)&h0; u.y = *(uint32_t*)&h1;
    u.z = *(uint32_t*)&h2; u.w = *(uint32_t*)&h3;
    *(uint4*)(g_W1h + idx) = u;
}

__global__ void __launch_bounds__(256)
convW2(const float* __restrict__ W2)
{
    size_t idx = ((size_t)blockIdx.x * 256 + threadIdx.x) * 8;   // 128 blocks exact
    float4 v0 = *(const float4*)(W2 + idx);
    float4 v1 = *(const float4*)(W2 + idx + 4);
    __half2 h0 = __floats2half2_rn(v0.x, v0.y);
    __half2 h1 = __floats2half2_rn(v0.z, v0.w);
    __half2 h2 = __floats2half2_rn(v1.x, v1.y);
    __half2 h3 = __floats2half2_rn(v1.z, v1.w);
    uint4 u;
    u.x = *(uint32_t*)&h0; u.y = *(uint32_t*)&h1;
    u.z = *(uint32_t*)&h2; u.w = *(uint32_t*)&h3;
    *(uint4*)(g_W2h + idx) = u;
}

// ---------------------------------------------------------------------------
// Kernel 1: H(fp16) = relu( (a kr c) @ W1 + b1 )
// 512 threads = 2 warp-groups; group handles half the i-range; triple-buffered
// cp.async fp16 W ring per group; fp16 m16n8k16 mma, fp32 accum + a-scale.
// ---------------------------------------------------------------------------
extern __shared__ char smem1[];

__global__ void __launch_bounds__(512, 1)
fused_k1(const float* __restrict__ inp1, const float* __restrict__ inp2,
         const float* __restrict__ b1)
{
    __half* c_s = (__half*)smem1;                       // [BM][CSTR]
    __half* b_s = (__half*)(smem1 + SMEM_C_BYTES);      // [2 grp][3][BS_HALVES]

    const int tid  = threadIdx.x;
    const int lane = tid & 31;
    const int wid  = tid >> 5;
    const int grp  = wid >> 3;
    const int gtid = tid & 255;
    const int gwid = wid & 7;
    const int wm   = gwid & 3;
    const int wn   = gwid >> 2;
    const int gq   = lane >> 2;
    const int tig  = lane & 3;
    const int m0   = blockIdx.y * BM;
    const int n0   = blockIdx.x * BN;

    const int igbase = grp ? 65 : 0;
    const int nig_g  = grp ? 64 : 65;

    const uint32_t c_base  = smem_u32(c_s);
    const uint32_t bring_u = smem_u32(b_s) + (uint32_t)(grp * 3 * BS_HALVES * 2);

    const int quad = lane >> 3, lrow = lane & 7;
    const int lmr  = (quad & 1) * 8 + lrow;
    const int lmc  = (quad >> 1) * 8;

    for (int idx = tid; idx < BM * PJ; idx += 512) {
        int m = idx / PJ, j = idx - m * PJ;
        float v = (j < I_SZ) ? inp2[(size_t)(m0 + m) * I_SZ + j]
                             : (j == I_SZ ? 1.0f : 0.0f);
        c_s[m * CSTR + j] = __float2half_rn(v);
    }
    __syncthreads();

    auto issueW = [&](int igl, int kt, int buf) {
        int ig = igbase + igl;
        #pragma unroll
        for (int q = 0; q < 2; ++q) {
            int ch  = gtid + q * 256;
            int row = ch >> 3;
            int c16 = ch & 7;
            int i   = ig * 2 + (row >> 5);
            int grow = i * P_SZ + kt * 32 + (row & 31);
            if (grow > FLATK - 1) grow = FLATK - 1;
            const __half* src = g_W1h + (size_t)grow * N1 + n0 + c16 * 8;
            uint32_t dst = bring_u + (uint32_t)(buf * BS_HALVES * 2 + row * 144 + c16 * 16);
            cpa16(dst, src);
        }
    };

    float h_acc[2][4][4];
    #pragma unroll
    for (int mt = 0; mt < 2; ++mt)
        #pragma unroll
        for (int nt = 0; nt < 4; ++nt)
            #pragma unroll
            for (int r = 0; r < 4; ++r) h_acc[mt][nt][r] = 0.0f;

    issueW(0, 0, 0); cpcommit();
    issueW(0, 1, 1); cpcommit();

    int bufR = 0, bufW = 2;

    for (int igl = 0; igl < nig_g; ++igl) {
        float av[2][4];
        #pragma unroll
        for (int g = 0; g < 2; ++g) {
            int i = (igbase + igl) * 2 + g;
            #pragma unroll
            for (int q = 0; q < 4; ++q) {
                int m = m0 + wm * 32 + (q >> 1) * 16 + (q & 1) * 8 + gq;
                av[g][q] = (i < I_SZ) ? __ldg(&inp1[(size_t)m * I_SZ + i])
                                      : (i == I_SZ ? 1.0f : 0.0f);
            }
        }

        float tmp[2][2][4][4];
        #pragma unroll
        for (int g = 0; g < 2; ++g)
            #pragma unroll
            for (int mt = 0; mt < 2; ++mt)
                #pragma unroll
                for (int nt = 0; nt < 4; ++nt)
                    #pragma unroll
                    for (int q = 0; q < 4; ++q) tmp[g][mt][nt][q] = 0.0f;

        for (int kt = 0; kt < NKT; ++kt) {
            const int j0 = kt * 32;
            uint32_t A[2][2][4];
            #pragma unroll
            for (int ks = 0; ks < 2; ++ks)
                #pragma unroll
                for (int mt = 0; mt < 2; ++mt) {
                    uint32_t addr = c_base + 2u * (uint32_t)(
                        (wm * 32 + mt * 16 + lmr) * CSTR + j0 + ks * 16 + lmc);
                    ldm_x4(A[ks][mt][0], A[ks][mt][1], A[ks][mt][2], A[ks][mt][3], addr);
                }

            cpwait1();
            bar_named(grp + 1);

            int kt2 = kt + 2, ig2 = igl;
            if (kt2 >= NKT) { kt2 -= NKT; ++ig2; }
            if (ig2 < nig_g) issueW(ig2, kt2, bufW);
            cpcommit();

            const uint32_t bb = bring_u + (uint32_t)(bufR * BS_HALVES * 2);
            #pragma unroll
            for (int g = 0; g < 2; ++g) {
                #pragma unroll
                for (int ks = 0; ks < 2; ++ks) {
                    #pragma unroll
                    for (int nh = 0; nh < 2; ++nh) {
                        uint32_t addr = bb + 2u * (uint32_t)(
                            (g * 32 + ks * 16 + lmr) * NSTR + wn * 32 + nh * 16 + lmc);
                        uint32_t b0, b1, b2, b3;
                        ldm_x4t(b0, b1, b2, b3, addr);
                        #pragma unroll
                        for (int mt = 0; mt < 2; ++mt) {
                            mma16(tmp[g][mt][nh * 2 + 0],
                                  A[ks][mt][0], A[ks][mt][1], A[ks][mt][2], A[ks][mt][3],
                                  b0, b1);
                            mma16(tmp[g][mt][nh * 2 + 1],
                                  A[ks][mt][0], A[ks][mt][1], A[ks][mt][2], A[ks][mt][3],
                                  b2, b3);
                        }
                    }
                }
            }
            bufR = (bufR == 2) ? 0 : bufR + 1;
            bufW = (bufW == 2) ? 0 : bufW + 1;
        }

        #pragma unroll
        for (int g = 0; g < 2; ++g)
            #pragma unroll
            for (int mt = 0; mt < 2; ++mt)
                #pragma unroll
                for (int nt = 0; nt < 4; ++nt)
                    #pragma unroll
                    for (int q = 0; q < 4; ++q)
                        h_acc[mt][nt][q] += av[g][mt * 2 + (q >> 1)] * tmp[g][mt][nt][q];
    }

    // ---- cross-group reduce through retired c_s region ----
    __syncthreads();
    float* xbuf = (float*)smem1;
    if (grp == 1) {
        #pragma unroll
        for (int mt = 0; mt < 2; ++mt)
            #pragma unroll
            for (int nt = 0; nt < 4; ++nt)
                *(float4*)&xbuf[gtid * 36 + (mt * 4 + nt) * 4] =
                    make_float4(h_acc[mt][nt][0], h_acc[mt][nt][1],
                                h_acc[mt][nt][2], h_acc[mt][nt][3]);
    }
    __syncthreads();
    if (grp == 0) {
        #pragma unroll
        for (int mt = 0; mt < 2; ++mt)
            #pragma unroll
            for (int nt = 0; nt < 4; ++nt) {
                float4 p = *(const float4*)&xbuf[gtid * 36 + (mt * 4 + nt) * 4];
                h_acc[mt][nt][0] += p.x; h_acc[mt][nt][1] += p.y;
                h_acc[mt][nt][2] += p.z; h_acc[mt][nt][3] += p.w;

                int n_base = n0 + wn * 32 + nt * 8 + tig * 2;
                float bv0 = b1[n_base], bv1 = b1[n_base + 1];
                #pragma unroll
                for (int h = 0; h < 2; ++h) {
                    int m = m0 + wm * 32 + mt * 16 + h * 8 + gq;
                    float v0 = fmaxf(h_acc[mt][nt][h * 2 + 0] + bv0, 0.0f);
                    float v1 = fmaxf(h_acc[mt][nt][h * 2 + 1] + bv1, 0.0f);
                    __half2 hv = __floats2half2_rn(v0, v1);
                    *(__half2*)&g_Hh[(size_t)m * N1 + n_base] = hv;
                }
            }
    }
}

// ---------------------------------------------------------------------------
// Kernel 2: out = relu( H @ W2 + b2 ) — fp16 tensor-core, fp32 accum.
// 256 threads = 8 warps (4 m x 2 n), tile 128x64, BK=64, triple-buffered
// cp.async, ldmatrix/ldmatrix.trans, same fragment layout as kernel 1.
// ---------------------------------------------------------------------------
extern __shared__ char smem2[];

__global__ void __launch_bounds__(256, 1)
fused_k2(const float* __restrict__ b2, float* __restrict__ out)
{
    const int tid  = threadIdx.x;
    const int lane = tid & 31;
    const int wid  = tid >> 5;
    const int wm   = wid & 3;
    const int wn   = wid >> 2;
    const int gq   = lane >> 2;
    const int tig  = lane & 3;
    const int m0   = blockIdx.y * BM;
    const int n0   = blockIdx.x * BN;

    const uint32_t sbase = smem_u32(smem2);

    const int quad = lane >> 3, lrow = lane & 7;
    const int lmr  = (quad & 1) * 8 + lrow;
    const int lmc  = (quad >> 1) * 8;

    // stage s (k0 = s*64) into buffer buf
    auto issue = [&](int s, int buf) {
        const int k0 = s * K2_BK;
        const uint32_t abase = sbase + (uint32_t)(buf * K2_BUF);
        #pragma unroll
        for (int q = 0; q < 4; ++q) {            // A: 1024 chunks (H tile 128x64)
            int ch  = tid + q * 256;
            int row = ch >> 3;                   // m-row 0..127
            int c16 = ch & 7;
            const __half* src = g_Hh + (size_t)(m0 + row) * N1 + k0 + c16 * 8;
            cpa16(abase + (uint32_t)(row * 144 + c16 * 16), src);
        }
        const uint32_t bbase = abase + K2_ABUF;
        #pragma unroll
        for (int q = 0; q < 2; ++q) {            // B: 512 chunks (W2 tile 64x64)
            int ch  = tid + q * 256;
            int row = ch >> 3;                   // k-row 0..63
            int c16 = ch & 7;
            const __half* src = g_W2h + (size_t)(k0 + row) * N1 + n0 + c16 * 8;
            cpa16(bbase + (uint32_t)(row * 144 + c16 * 16), src);
        }
    };

    float acc[2][4][4];
    #pragma unroll
    for (int mt = 0; mt < 2; ++mt)
        #pragma unroll
        for (int nt = 0; nt < 4; ++nt)
            #pragma unroll
            for (int r = 0; r < 4; ++r) acc[mt][nt][r] = 0.0f;

    issue(0, 0); cpcommit();
    issue(1, 1); cpcommit();

    int bufR = 0, bufW = 2;
    const int NST = N1 / K2_BK;   // 8 stages

    for (int s = 0; s < NST; ++s) {
        cpwait1();
        __syncthreads();

        if (s + 2 < NST) issue(s + 2, bufW);
        cpcommit();

        const uint32_t abase = sbase + (uint32_t)(bufR * K2_BUF);
        const uint32_t bbase = abase + K2_ABUF;

        #pragma unroll
        for (int ks = 0; ks < 4; ++ks) {
            uint32_t A[2][4];
            #pragma unroll
            for (int mt = 0; mt < 2; ++mt) {
                uint32_t addr = abase + (uint32_t)(
                    (wm * 32 + mt * 16 + lmr) * 144 + (ks * 16 + lmc) * 2);
                ldm_x4(A[mt][0], A[mt][1], A[mt][2], A[mt][3], addr);
            }
            #pragma unroll
            for (int nh = 0; nh < 2; ++nh) {
                uint32_t addr = bbase + (uint32_t)(
                    (ks * 16 + lmr) * 144 + (wn * 32 + nh * 16 + lmc) * 2);
                uint32_t b0, b1, b2, b3;
                ldm_x4t(b0, b1, b2, b3, addr);
                #pragma unroll
                for (int mt = 0; mt < 2; ++mt) {
                    mma16(acc[mt][nh * 2 + 0], A[mt][0], A[mt][1], A[mt][2], A[mt][3], b0, b1);
                    mma16(acc[mt][nh * 2 + 1], A[mt][0], A[mt][1], A[mt][2], A[mt][3], b2, b3);
                }
            }
        }
        bufR = (bufR == 2) ? 0 : bufR + 1;
        bufW = (bufW == 2) ? 0 : bufW + 1;
    }

    // epilogue: + b2, relu, write out (fp32)
    #pragma unroll
    for (int mt = 0; mt < 2; ++mt)
        #pragma unroll
        for (int nt = 0; nt < 4; ++nt) {
            int n_base = n0 + wn * 32 + nt * 8 + tig * 2;
            float bv0 = b2[n_base], bv1 = b2[n_base + 1];
            #pragma unroll
            for (int h = 0; h < 2; ++h) {
                int m = m0 + wm * 32 + mt * 16 + h * 8 + gq;
                float v0 = fmaxf(acc[mt][nt][h * 2 + 0] + bv0, 0.0f);
                float v1 = fmaxf(acc[mt][nt][h * 2 + 1] + bv1, 0.0f);
                *(float2*)&out[(size_t)m * N1 + n_base] = make_float2(v0, v1);
            }
        }
}

// ---------------------------------------------------------------------------
extern "C" void kernel_launch(void* const* d_in, const int* in_sizes, int n_in,
                              void* d_out, int out_size)
{
    const float* inp1 = (const float*)d_in[0];   // [2048, 256]
    const float* inp2 = (const float*)d_in[1];   // [2048, 256]
    const float* W1   = (const float*)d_in[2];   // [66049, 512]
    const float* b1   = (const float*)d_in[3];   // [512]
    const float* W2   = (const float*)d_in[4];   // [512, 512]
    const float* b2   = (const float*)d_in[5];   // [512]
    (void)in_sizes; (void)n_in; (void)out_size;

    convW<<<16513, 256>>>(W1);          // ceil(33,817,088 / 2048)
    convW2<<<128, 256>>>(W2);           // 512*512 / 2048 exact

    cudaFuncSetAttribute(fused_k1, cudaFuncAttributeMaxDynamicSharedMemorySize, SMEM_TOTAL);
    fused_k1<<<dim3(N1 / BN, B_SZ / BM), 512, SMEM_TOTAL>>>(inp1, inp2, b1);

    cudaFuncSetAttribute(fused_k2, cudaFuncAttributeMaxDynamicSharedMemorySize, K2_SMEM);
    fused_k2<<<dim3(N1 / BN, B_SZ / BM), 256, K2_SMEM>>>(b2, (float*)d_out);
}

// round 10
// speedup vs baseline: 2.5128x; 1.1116x over previous
#include <cuda_runtime.h>
#include <cuda_fp16.h>
#include <cstdint>
#include <cstddef>

// ---------------- problem constants ----------------
#define B_SZ   2048
#define I_SZ   256
#define P_SZ   257
#define FLATK  66049        // 257*257
#define N1     512

// ---------------- kernel-1 tiling (main part: i<256, j<256) ----------------
#define BM     128
#define BN     64
#define CSTR   264          // c_s row stride in halves (528B: conflict-free ldmatrix)
#define NSTR   72           // B tile n stride in halves (144B rows, conflict-free)
#define NKT    8            // j tiles per i (8*32 = 256, exact!)
#define NIG_G  64           // i-groups per warp-group (2*64*2 groups = 256 i's exact)
#define BS_HALVES (64*NSTR)               // one B buffer (9216 B)
#define SMEM_C_BYTES (BM*CSTR*2)          // 67584
#define SMEM_TOTAL   (SMEM_C_BYTES + 6*BS_HALVES*2)  // 122880

// ---------------- k2/border tiling ----------------
#define K2_ABUF  18432      // 128 rows * 72 halves * 2B
#define K2_BBUF  9216       // 64 rows * 72 halves * 2B
#define K2_BUF   (K2_ABUF + K2_BBUF)
#define K2_SMEM  (3 * K2_BUF)             // 82944

#define AB_K     576        // border K padded: 513 -> 9*64

// statics
__device__ __half g_W1h[(size_t)FLATK * N1];     // 67.6 MB
__device__ __half g_W2h[(size_t)N1 * N1];        // 0.5 MB
__device__ __half g_Hh[(size_t)B_SZ * N1];       // 2 MB
__device__ __half g_Ab[(size_t)B_SZ * AB_K];     // 2.4 MB  [cext | a | 0pad]
__device__ float  g_Bord[(size_t)B_SZ * N1];     // 4 MB  border partial + b1

__device__ __forceinline__ void mma16(float* d, uint32_t a0, uint32_t a1,
                                      uint32_t a2, uint32_t a3,
                                      uint32_t b0, uint32_t b1) {
    asm volatile(
        "mma.sync.aligned.m16n8k16.row.col.f32.f16.f16.f32 "
        "{%0,%1,%2,%3}, {%4,%5,%6,%7}, {%8,%9}, {%0,%1,%2,%3};"
        : "+f"(d[0]), "+f"(d[1]), "+f"(d[2]), "+f"(d[3])
        : "r"(a0), "r"(a1), "r"(a2), "r"(a3), "r"(b0), "r"(b1));
}
__device__ __forceinline__ uint32_t smem_u32(const void* p) {
    uint32_t a;
    asm("{ .reg .u64 t; cvta.to.shared.u64 t, %1; cvt.u32.u64 %0, t; }" : "=r"(a) : "l"(p));
    return a;
}
__device__ __forceinline__ void ldm_x4(uint32_t& r0, uint32_t& r1, uint32_t& r2,
                                       uint32_t& r3, uint32_t a) {
    asm volatile("ldmatrix.sync.aligned.m8n8.x4.shared.b16 {%0,%1,%2,%3}, [%4];"
                 : "=r"(r0), "=r"(r1), "=r"(r2), "=r"(r3) : "r"(a));
}
__device__ __forceinline__ void ldm_x4t(uint32_t& r0, uint32_t& r1, uint32_t& r2,
                                        uint32_t& r3, uint32_t a) {
    asm volatile("ldmatrix.sync.aligned.m8n8.x4.trans.shared.b16 {%0,%1,%2,%3}, [%4];"
                 : "=r"(r0), "=r"(r1), "=r"(r2), "=r"(r3) : "r"(a));
}
__device__ __forceinline__ void cpa16(uint32_t s, const void* g) {
    asm volatile("cp.async.cg.shared.global [%0], [%1], 16;" :: "r"(s), "l"(g));
}
__device__ __forceinline__ void cpcommit() { asm volatile("cp.async.commit_group;"); }
__device__ __forceinline__ void cpwait1()  { asm volatile("cp.async.wait_group 1;"); }
__device__ __forceinline__ void bar_named(int id) {
    asm volatile("bar.sync %0, 256;" :: "r"(id) : "memory");
}

// ---------------------------------------------------------------------------
// Converters
// ---------------------------------------------------------------------------
__global__ void __launch_bounds__(256)
convW(const float* __restrict__ W1)
{
    const size_t total = (size_t)FLATK * N1;   // 33,817,088 (div by 8)
    size_t idx = ((size_t)blockIdx.x * 256 + threadIdx.x) * 8;
    if (idx >= total) return;
    float4 v0 = *(const float4*)(W1 + idx);
    float4 v1 = *(const float4*)(W1 + idx + 4);
    __half2 h0 = __floats2half2_rn(v0.x, v0.y);
    __half2 h1 = __floats2half2_rn(v0.z, v0.w);
    __half2 h2 = __floats2half2_rn(v1.x, v1.y);
    __half2 h3 = __floats2half2_rn(v1.z, v1.w);
    uint4 u;
    u.x = *(uint32_t*)&h0; u.y = *(uint32_t*)&h1;
    u.z = *(uint32_t*)&h2; u.w = *(uint32_t*)&h3;
    *(uint4*)(g_W1h + idx) = u;
}

__global__ void __launch_bounds__(256)
convW2(const float* __restrict__ W2)
{
    size_t idx = ((size_t)blockIdx.x * 256 + threadIdx.x) * 8;   // 128 blocks exact
    float4 v0 = *(const float4*)(W2 + idx);
    float4 v1 = *(const float4*)(W2 + idx + 4);
    __half2 h0 = __floats2half2_rn(v0.x, v0.y);
    __half2 h1 = __floats2half2_rn(v0.z, v0.w);
    __half2 h2 = __floats2half2_rn(v1.x, v1.y);
    __half2 h3 = __floats2half2_rn(v1.z, v1.w);
    uint4 u;
    u.x = *(uint32_t*)&h0; u.y = *(uint32_t*)&h1;
    u.z = *(uint32_t*)&h2; u.w = *(uint32_t*)&h3;
    *(uint4*)(g_W2h + idx) = u;
}

// g_Ab[m][k]: k<256 -> c[m,k]; k==256 -> 1; 257<=k<513 -> a[m,k-257]; else 0
__global__ void __launch_bounds__(256)
convA(const float* __restrict__ inp1, const float* __restrict__ inp2)
{
    int t = blockIdx.x * 256 + threadIdx.x;     // 2048*144 = 294912 tasks
    int m = t / (AB_K / 4);
    int c4 = (t - m * (AB_K / 4)) * 4;
    __half h[4];
    #pragma unroll
    for (int e = 0; e < 4; ++e) {
        int col = c4 + e;
        float v;
        if (col < I_SZ)       v = inp2[(size_t)m * I_SZ + col];
        else if (col == I_SZ) v = 1.0f;
        else if (col < 513)   v = inp1[(size_t)m * I_SZ + (col - 257)];
        else                  v = 0.0f;
        h[e] = __float2half_rn(v);
    }
    uint2 u;
    u.x = *(uint32_t*)&h[0];
    u.y = *(uint32_t*)&h[2];
    *(uint2*)&g_Ab[(size_t)m * AB_K + c4] = u;
}

// ---------------------------------------------------------------------------
// Border kernel: g_Bord = [cext|a] @ Wb + b1  (pre-relu fp32 partial)
// Wb row k: k<257 -> W1h[65792+k]; 257<=k<513 -> W1h[(k-257)*257+256]; else dummy
// ---------------------------------------------------------------------------
extern __shared__ char smemB[];

__global__ void __launch_bounds__(256, 1)
border_k(const float* __restrict__ b1)
{
    const int tid  = threadIdx.x;
    const int lane = tid & 31;
    const int wid  = tid >> 5;
    const int wm   = wid & 3;
    const int wn   = wid >> 2;
    const int gq   = lane >> 2;
    const int tig  = lane & 3;
    const int m0   = blockIdx.y * BM;
    const int n0   = blockIdx.x * BN;

    const uint32_t sbase = smem_u32(smemB);
    const int quad = lane >> 3, lrow = lane & 7;
    const int lmr  = (quad & 1) * 8 + lrow;
    const int lmc  = (quad >> 1) * 8;

    auto issue = [&](int s, int buf) {
        const int k0 = s * 64;
        const uint32_t abase = sbase + (uint32_t)(buf * K2_BUF);
        #pragma unroll
        for (int q = 0; q < 4; ++q) {
            int ch  = tid + q * 256;
            int row = ch >> 3;
            int c16 = ch & 7;
            const __half* src = g_Ab + (size_t)(m0 + row) * AB_K + k0 + c16 * 8;
            cpa16(abase + (uint32_t)(row * 144 + c16 * 16), src);
        }
        const uint32_t bbase = abase + K2_ABUF;
        #pragma unroll
        for (int q = 0; q < 2; ++q) {
            int ch  = tid + q * 256;
            int row = ch >> 3;
            int c16 = ch & 7;
            int kk  = k0 + row;
            int grow;
            if (kk < 257)      grow = 65792 + kk;            // i=256 block
            else if (kk < 513) grow = (kk - 257) * P_SZ + 256; // j=256 column
            else               grow = 0;                     // A=0 pad
            const __half* src = g_W1h + (size_t)grow * N1 + n0 + c16 * 8;
            cpa16(bbase + (uint32_t)(row * 144 + c16 * 16), src);
        }
    };

    float acc[2][4][4];
    #pragma unroll
    for (int mt = 0; mt < 2; ++mt)
        #pragma unroll
        for (int nt = 0; nt < 4; ++nt)
            #pragma unroll
            for (int r = 0; r < 4; ++r) acc[mt][nt][r] = 0.0f;

    issue(0, 0); cpcommit();
    issue(1, 1); cpcommit();

    int bufR = 0, bufW = 2;
    const int NST = AB_K / 64;   // 9

    for (int s = 0; s < NST; ++s) {
        cpwait1();
        __syncthreads();
        if (s + 2 < NST) issue(s + 2, bufW);
        cpcommit();

        const uint32_t abase = sbase + (uint32_t)(bufR * K2_BUF);
        const uint32_t bbase = abase + K2_ABUF;

        #pragma unroll
        for (int ks = 0; ks < 4; ++ks) {
            uint32_t A[2][4];
            #pragma unroll
            for (int mt = 0; mt < 2; ++mt) {
                uint32_t addr = abase + (uint32_t)(
                    (wm * 32 + mt * 16 + lmr) * 144 + (ks * 16 + lmc) * 2);
                ldm_x4(A[mt][0], A[mt][1], A[mt][2], A[mt][3], addr);
            }
            #pragma unroll
            for (int nh = 0; nh < 2; ++nh) {
                uint32_t addr = bbase + (uint32_t)(
                    (ks * 16 + lmr) * 144 + (wn * 32 + nh * 16 + lmc) * 2);
                uint32_t b0, b1r, b2r, b3;
                ldm_x4t(b0, b1r, b2r, b3, addr);
                #pragma unroll
                for (int mt = 0; mt < 2; ++mt) {
                    mma16(acc[mt][nh * 2 + 0], A[mt][0], A[mt][1], A[mt][2], A[mt][3], b0, b1r);
                    mma16(acc[mt][nh * 2 + 1], A[mt][0], A[mt][1], A[mt][2], A[mt][3], b2r, b3);
                }
            }
        }
        bufR = (bufR == 2) ? 0 : bufR + 1;
        bufW = (bufW == 2) ? 0 : bufW + 1;
    }

    // epilogue: + b1, NO relu, fp32 store to g_Bord
    #pragma unroll
    for (int mt = 0; mt < 2; ++mt)
        #pragma unroll
        for (int nt = 0; nt < 4; ++nt) {
            int n_base = n0 + wn * 32 + nt * 8 + tig * 2;
            float bv0 = b1[n_base], bv1 = b1[n_base + 1];
            #pragma unroll
            for (int h = 0; h < 2; ++h) {
                int m = m0 + wm * 32 + mt * 16 + h * 8 + gq;
                *(float2*)&g_Bord[(size_t)m * N1 + n_base] =
                    make_float2(acc[mt][nt][h * 2 + 0] + bv0,
                                acc[mt][nt][h * 2 + 1] + bv1);
            }
        }
}

// ---------------------------------------------------------------------------
// Kernel 1 (main part): i in [0,256), j in [0,256). No padding, no clamps.
// H(fp16) = relu( main + g_Bord )
// ---------------------------------------------------------------------------
extern __shared__ char smem1[];

__global__ void __launch_bounds__(512, 1)
fused_k1(const float* __restrict__ inp1, const float* __restrict__ inp2)
{
    __half* c_s = (__half*)smem1;                       // [BM][CSTR]
    __half* b_s = (__half*)(smem1 + SMEM_C_BYTES);      // [2 grp][3][BS_HALVES]

    const int tid  = threadIdx.x;
    const int lane = tid & 31;
    const int wid  = tid >> 5;
    const int grp  = wid >> 3;
    const int gtid = tid & 255;
    const int gwid = wid & 7;
    const int wm   = gwid & 3;
    const int wn   = gwid >> 2;
    const int gq   = lane >> 2;
    const int tig  = lane & 3;
    const int m0   = blockIdx.y * BM;
    const int n0   = blockIdx.x * BN;

    const int igbase = grp * NIG_G;

    const uint32_t c_base  = smem_u32(c_s);
    const uint32_t bring_u = smem_u32(b_s) + (uint32_t)(grp * 3 * BS_HALVES * 2);

    const int quad = lane >> 3, lrow = lane & 7;
    const int lmr  = (quad & 1) * 8 + lrow;
    const int lmc  = (quad >> 1) * 8;

    // stage c tile (j 0..255 only)
    for (int idx = tid; idx < BM * 256; idx += 512) {
        int m = idx >> 8, j = idx & 255;
        c_s[m * CSTR + j] = __float2half_rn(inp2[(size_t)(m0 + m) * I_SZ + j]);
    }
    __syncthreads();

    auto issueW = [&](int igl, int kt, int buf) {
        int ig = igbase + igl;
        #pragma unroll
        for (int q = 0; q < 2; ++q) {
            int ch  = gtid + q * 256;
            int row = ch >> 3;
            int c16 = ch & 7;
            int i   = ig * 2 + (row >> 5);
            int grow = i * P_SZ + kt * 32 + (row & 31);   // always < FLATK
            const __half* src = g_W1h + (size_t)grow * N1 + n0 + c16 * 8;
            uint32_t dst = bring_u + (uint32_t)(buf * BS_HALVES * 2 + row * 144 + c16 * 16);
            cpa16(dst, src);
        }
    };

    float h_acc[2][4][4];
    #pragma unroll
    for (int mt = 0; mt < 2; ++mt)
        #pragma unroll
        for (int nt = 0; nt < 4; ++nt)
            #pragma unroll
            for (int r = 0; r < 4; ++r) h_acc[mt][nt][r] = 0.0f;

    issueW(0, 0, 0); cpcommit();
    issueW(0, 1, 1); cpcommit();

    int bufR = 0, bufW = 2;

    for (int igl = 0; igl < NIG_G; ++igl) {
        float av[2][4];
        #pragma unroll
        for (int g = 0; g < 2; ++g) {
            int i = (igbase + igl) * 2 + g;     // < 256 always
            #pragma unroll
            for (int q = 0; q < 4; ++q) {
                int m = m0 + wm * 32 + (q >> 1) * 16 + (q & 1) * 8 + gq;
                av[g][q] = __ldg(&inp1[(size_t)m * I_SZ + i]);
            }
        }

        float tmp[2][2][4][4];
        #pragma unroll
        for (int g = 0; g < 2; ++g)
            #pragma unroll
            for (int mt = 0; mt < 2; ++mt)
                #pragma unroll
                for (int nt = 0; nt < 4; ++nt)
                    #pragma unroll
                    for (int q = 0; q < 4; ++q) tmp[g][mt][nt][q] = 0.0f;

        for (int kt = 0; kt < NKT; ++kt) {
            const int j0 = kt * 32;
            uint32_t A[2][2][4];
            #pragma unroll
            for (int ks = 0; ks < 2; ++ks)
                #pragma unroll
                for (int mt = 0; mt < 2; ++mt) {
                    uint32_t addr = c_base + 2u * (uint32_t)(
                        (wm * 32 + mt * 16 + lmr) * CSTR + j0 + ks * 16 + lmc);
                    ldm_x4(A[ks][mt][0], A[ks][mt][1], A[ks][mt][2], A[ks][mt][3], addr);
                }

            cpwait1();
            bar_named(grp + 1);

            int kt2 = kt + 2, ig2 = igl;
            if (kt2 >= NKT) { kt2 -= NKT; ++ig2; }
            if (ig2 < NIG_G) issueW(ig2, kt2, bufW);
            cpcommit();

            const uint32_t bb = bring_u + (uint32_t)(bufR * BS_HALVES * 2);
            #pragma unroll
            for (int g = 0; g < 2; ++g) {
                #pragma unroll
                for (int ks = 0; ks < 2; ++ks) {
                    #pragma unroll
                    for (int nh = 0; nh < 2; ++nh) {
                        uint32_t addr = bb + 2u * (uint32_t)(
                            (g * 32 + ks * 16 + lmr) * NSTR + wn * 32 + nh * 16 + lmc);
                        uint32_t b0, b1, b2, b3;
                        ldm_x4t(b0, b1, b2, b3, addr);
                        #pragma unroll
                        for (int mt = 0; mt < 2; ++mt) {
                            mma16(tmp[g][mt][nh * 2 + 0],
                                  A[ks][mt][0], A[ks][mt][1], A[ks][mt][2], A[ks][mt][3],
                                  b0, b1);
                            mma16(tmp[g][mt][nh * 2 + 1],
                                  A[ks][mt][0], A[ks][mt][1], A[ks][mt][2], A[ks][mt][3],
                                  b2, b3);
                        }
                    }
                }
            }
            bufR = (bufR == 2) ? 0 : bufR + 1;
            bufW = (bufW == 2) ? 0 : bufW + 1;
        }

        #pragma unroll
        for (int g = 0; g < 2; ++g)
            #pragma unroll
            for (int mt = 0; mt < 2; ++mt)
                #pragma unroll
                for (int nt = 0; nt < 4; ++nt)
                    #pragma unroll
                    for (int q = 0; q < 4; ++q)
                        h_acc[mt][nt][q] += av[g][mt * 2 + (q >> 1)] * tmp[g][mt][nt][q];
    }

    // cross-group reduce through retired c_s region
    __syncthreads();
    float* xbuf = (float*)smem1;
    if (grp == 1) {
        #pragma unroll
        for (int mt = 0; mt < 2; ++mt)
            #pragma unroll
            for (int nt = 0; nt < 4; ++nt)
                *(float4*)&xbuf[gtid * 36 + (mt * 4 + nt) * 4] =
                    make_float4(h_acc[mt][nt][0], h_acc[mt][nt][1],
                                h_acc[mt][nt][2], h_acc[mt][nt][3]);
    }
    __syncthreads();
    if (grp == 0) {
        #pragma unroll
        for (int mt = 0; mt < 2; ++mt)
            #pragma unroll
            for (int nt = 0; nt < 4; ++nt) {
                float4 p = *(const float4*)&xbuf[gtid * 36 + (mt * 4 + nt) * 4];
                h_acc[mt][nt][0] += p.x; h_acc[mt][nt][1] += p.y;
                h_acc[mt][nt][2] += p.z; h_acc[mt][nt][3] += p.w;

                int n_base = n0 + wn * 32 + nt * 8 + tig * 2;
                #pragma unroll
                for (int h = 0; h < 2; ++h) {
                    int m = m0 + wm * 32 + mt * 16 + h * 8 + gq;
                    float2 bo = *(const float2*)&g_Bord[(size_t)m * N1 + n_base];
                    float v0 = fmaxf(h_acc[mt][nt][h * 2 + 0] + bo.x, 0.0f);
                    float v1 = fmaxf(h_acc[mt][nt][h * 2 + 1] + bo.y, 0.0f);
                    __half2 hv = __floats2half2_rn(v0, v1);
                    *(__half2*)&g_Hh[(size_t)m * N1 + n_base] = hv;
                }
            }
    }
}

// ---------------------------------------------------------------------------
// Kernel 2: out = relu( H @ W2 + b2 ) — fp16 tensor-core, fp32 accum.
// ---------------------------------------------------------------------------
extern __shared__ char smem2[];

__global__ void __launch_bounds__(256, 1)
fused_k2(const float* __restrict__ b2, float* __restrict__ out)
{
    const int tid  = threadIdx.x;
    const int lane = tid & 31;
    const int wid  = tid >> 5;
    const int wm   = wid & 3;
    const int wn   = wid >> 2;
    const int gq   = lane >> 2;
    const int tig  = lane & 3;
    const int m0   = blockIdx.y * BM;
    const int n0   = blockIdx.x * BN;

    const uint32_t sbase = smem_u32(smem2);
    const int quad = lane >> 3, lrow = lane & 7;
    const int lmr  = (quad & 1) * 8 + lrow;
    const int lmc  = (quad >> 1) * 8;

    auto issue = [&](int s, int buf) {
        const int k0 = s * 64;
        const uint32_t abase = sbase + (uint32_t)(buf * K2_BUF);
        #pragma unroll
        for (int q = 0; q < 4; ++q) {
            int ch  = tid + q * 256;
            int row = ch >> 3;
            int c16 = ch & 7;
            const __half* src = g_Hh + (size_t)(m0 + row) * N1 + k0 + c16 * 8;
            cpa16(abase + (uint32_t)(row * 144 + c16 * 16), src);
        }
        const uint32_t bbase = abase + K2_ABUF;
        #pragma unroll
        for (int q = 0; q < 2; ++q) {
            int ch  = tid + q * 256;
            int row = ch >> 3;
            int c16 = ch & 7;
            const __half* src = g_W2h + (size_t)(k0 + row) * N1 + n0 + c16 * 8;
            cpa16(bbase + (uint32_t)(row * 144 + c16 * 16), src);
        }
    };

    float acc[2][4][4];
    #pragma unroll
    for (int mt = 0; mt < 2; ++mt)
        #pragma unroll
        for (int nt = 0; nt < 4; ++nt)
            #pragma unroll
            for (int r = 0; r < 4; ++r) acc[mt][nt][r] = 0.0f;

    issue(0, 0); cpcommit();
    issue(1, 1); cpcommit();

    int bufR = 0, bufW = 2;
    const int NST = N1 / 64;   // 8

    for (int s = 0; s < NST; ++s) {
        cpwait1();
        __syncthreads();
        if (s + 2 < NST) issue(s + 2, bufW);
        cpcommit();

        const uint32_t abase = sbase + (uint32_t)(bufR * K2_BUF);
        const uint32_t bbase = abase + K2_ABUF;

        #pragma unroll
        for (int ks = 0; ks < 4; ++ks) {
            uint32_t A[2][4];
            #pragma unroll
            for (int mt = 0; mt < 2; ++mt) {
                uint32_t addr = abase + (uint32_t)(
                    (wm * 32 + mt * 16 + lmr) * 144 + (ks * 16 + lmc) * 2);
                ldm_x4(A[mt][0], A[mt][1], A[mt][2], A[mt][3], addr);
            }
            #pragma unroll
            for (int nh = 0; nh < 2; ++nh) {
                uint32_t addr = bbase + (uint32_t)(
                    (ks * 16 + lmr) * 144 + (wn * 32 + nh * 16 + lmc) * 2);
                uint32_t b0, b1, b2, b3;
                ldm_x4t(b0, b1, b2, b3, addr);
                #pragma unroll
                for (int mt = 0; mt < 2; ++mt) {
                    mma16(acc[mt][nh * 2 + 0], A[mt][0], A[mt][1], A[mt][2], A[mt][3], b0, b1);
                    mma16(acc[mt][nh * 2 + 1], A[mt][0], A[mt][1], A[mt][2], A[mt][3], b2, b3);
                }
            }
        }
        bufR = (bufR == 2) ? 0 : bufR + 1;
        bufW = (bufW == 2) ? 0 : bufW + 1;
    }

    #pragma unroll
    for (int mt = 0; mt < 2; ++mt)
        #pragma unroll
        for (int nt = 0; nt < 4; ++nt) {
            int n_base = n0 + wn * 32 + nt * 8 + tig * 2;
            float bv0 = b2[n_base], bv1 = b2[n_base + 1];
            #pragma unroll
            for (int h = 0; h < 2; ++h) {
                int m = m0 + wm * 32 + mt * 16 + h * 8 + gq;
                float v0 = fmaxf(acc[mt][nt][h * 2 + 0] + bv0, 0.0f);
                float v1 = fmaxf(acc[mt][nt][h * 2 + 1] + bv1, 0.0f);
                *(float2*)&out[(size_t)m * N1 + n_base] = make_float2(v0, v1);
            }
        }
}

// ---------------------------------------------------------------------------
extern "C" void kernel_launch(void* const* d_in, const int* in_sizes, int n_in,
                              void* d_out, int out_size)
{
    const float* inp1 = (const float*)d_in[0];   // [2048, 256]
    const float* inp2 = (const float*)d_in[1];   // [2048, 256]
    const float* W1   = (const float*)d_in[2];   // [66049, 512]
    const float* b1   = (const float*)d_in[3];   // [512]
    const float* W2   = (const float*)d_in[4];   // [512, 512]
    const float* b2   = (const float*)d_in[5];   // [512]
    (void)in_sizes; (void)n_in; (void)out_size;

    convW<<<16513, 256>>>(W1);
    convW2<<<128, 256>>>(W2);
    convA<<<(B_SZ * (AB_K / 4)) / 256, 256>>>(inp1, inp2);   // 1152 blocks

    cudaFuncSetAttribute(border_k, cudaFuncAttributeMaxDynamicSharedMemorySize, K2_SMEM);
    border_k<<<dim3(N1 / BN, B_SZ / BM), 256, K2_SMEM>>>(b1);

    cudaFuncSetAttribute(fused_k1, cudaFuncAttributeMaxDynamicSharedMemorySize, SMEM_TOTAL);
    fused_k1<<<dim3(N1 / BN, B_SZ / BM), 512, SMEM_TOTAL>>>(inp1, inp2);

    cudaFuncSetAttribute(fused_k2, cudaFuncAttributeMaxDynamicSharedMemorySize, K2_SMEM);
    fused_k2<<<dim3(N1 / BN, B_SZ / BM), 256, K2_SMEM>>>(b2, (float*)d_out);
}

// round 12
// speedup vs baseline: 2.5556x; 1.0170x over previous
#include <cuda_runtime.h>
#include <cuda_fp16.h>
#include <cstdint>
#include <cstddef>

// ---------------- problem constants ----------------
#define B_SZ   2048
#define I_SZ   256
#define P_SZ   257
#define FLATK  66049        // 257*257
#define N1     512

// ---------------- kernel-1 tiling (main part: i<256, j<256) ----------------
#define BM     128
#define BN     64
#define CSTR   264          // c_s row stride in halves
#define NSTR   72           // B tile n stride in halves
#define NKT    8            // j tiles per i (exact 256)
#define NIG_G  64           // i-groups per warp-group
#define BS_HALVES (64*NSTR)
#define SMEM_C_BYTES (BM*CSTR*2)          // 67584
#define SMEM_TOTAL   (SMEM_C_BYTES + 6*BS_HALVES*2)  // 122880

// ---------------- k2/border tiling ----------------
#define K2_ABUF  18432
#define K2_BBUF  9216
#define K2_BUF   (K2_ABUF + K2_BBUF)
#define K2_SMEM  (3 * K2_BUF)             // 82944

#define AB_K     576        // border K padded: 513 -> 9*64
#define NWORK    20         // border worker CTAs (148 - 128)

// statics
__device__ __half g_W1h[(size_t)FLATK * N1];
__device__ __half g_W2h[(size_t)N1 * N1];
__device__ __half g_Hh[(size_t)B_SZ * N1];
__device__ __half g_Ab[(size_t)B_SZ * AB_K];
__device__ float  g_Bord[(size_t)B_SZ * N1];
__device__ int    g_done[128];

__device__ __forceinline__ void mma16(float* d, uint32_t a0, uint32_t a1,
                                      uint32_t a2, uint32_t a3,
                                      uint32_t b0, uint32_t b1) {
    asm volatile(
        "mma.sync.aligned.m16n8k16.row.col.f32.f16.f16.f32 "
        "{%0,%1,%2,%3}, {%4,%5,%6,%7}, {%8,%9}, {%0,%1,%2,%3};"
        : "+f"(d[0]), "+f"(d[1]), "+f"(d[2]), "+f"(d[3])
        : "r"(a0), "r"(a1), "r"(a2), "r"(a3), "r"(b0), "r"(b1));
}
__device__ __forceinline__ uint32_t smem_u32(const void* p) {
    uint32_t a;
    asm("{ .reg .u64 t; cvta.to.shared.u64 t, %1; cvt.u32.u64 %0, t; }" : "=r"(a) : "l"(p));
    return a;
}
__device__ __forceinline__ void ldm_x4(uint32_t& r0, uint32_t& r1, uint32_t& r2,
                                       uint32_t& r3, uint32_t a) {
    asm volatile("ldmatrix.sync.aligned.m8n8.x4.shared.b16 {%0,%1,%2,%3}, [%4];"
                 : "=r"(r0), "=r"(r1), "=r"(r2), "=r"(r3) : "r"(a));
}
__device__ __forceinline__ void ldm_x4t(uint32_t& r0, uint32_t& r1, uint32_t& r2,
                                        uint32_t& r3, uint32_t a) {
    asm volatile("ldmatrix.sync.aligned.m8n8.x4.trans.shared.b16 {%0,%1,%2,%3}, [%4];"
                 : "=r"(r0), "=r"(r1), "=r"(r2), "=r"(r3) : "r"(a));
}
__device__ __forceinline__ void cpa16(uint32_t s, const void* g) {
    asm volatile("cp.async.cg.shared.global [%0], [%1], 16;" :: "r"(s), "l"(g));
}
__device__ __forceinline__ void cpcommit() { asm volatile("cp.async.commit_group;"); }
__device__ __forceinline__ void cpwait1()  { asm volatile("cp.async.wait_group 1;"); }
__device__ __forceinline__ void bar_named(int id) {
    asm volatile("bar.sync %0, 256;" :: "r"(id) : "memory");
}

// ---------------------------------------------------------------------------
// Converters + flag reset
// ---------------------------------------------------------------------------
__global__ void __launch_bounds__(256)
convW(const float* __restrict__ W1)
{
    const size_t total = (size_t)FLATK * N1;
    size_t idx = ((size_t)blockIdx.x * 256 + threadIdx.x) * 8;
    if (idx >= total) return;
    float4 v0 = *(const float4*)(W1 + idx);
    float4 v1 = *(const float4*)(W1 + idx + 4);
    __half2 h0 = __floats2half2_rn(v0.x, v0.y);
    __half2 h1 = __floats2half2_rn(v0.z, v0.w);
    __half2 h2 = __floats2half2_rn(v1.x, v1.y);
    __half2 h3 = __floats2half2_rn(v1.z, v1.w);
    uint4 u;
    u.x = *(uint32_t*)&h0; u.y = *(uint32_t*)&h1;
    u.z = *(uint32_t*)&h2; u.w = *(uint32_t*)&h3;
    *(uint4*)(g_W1h + idx) = u;
}

__global__ void __launch_bounds__(256)
convW2(const float* __restrict__ W2)
{
    size_t idx = ((size_t)blockIdx.x * 256 + threadIdx.x) * 8;
    float4 v0 = *(const float4*)(W2 + idx);
    float4 v1 = *(const float4*)(W2 + idx + 4);
    __half2 h0 = __floats2half2_rn(v0.x, v0.y);
    __half2 h1 = __floats2half2_rn(v0.z, v0.w);
    __half2 h2 = __floats2half2_rn(v1.x, v1.y);
    __half2 h3 = __floats2half2_rn(v1.z, v1.w);
    uint4 u;
    u.x = *(uint32_t*)&h0; u.y = *(uint32_t*)&h1;
    u.z = *(uint32_t*)&h2; u.w = *(uint32_t*)&h3;
    *(uint4*)(g_W2h + idx) = u;
}

__global__ void __launch_bounds__(256)
convA(const float* __restrict__ inp1, const float* __restrict__ inp2)
{
    int t = blockIdx.x * 256 + threadIdx.x;
    int m = t / (AB_K / 4);
    int c4 = (t - m * (AB_K / 4)) * 4;
    __half h[4];
    #pragma unroll
    for (int e = 0; e < 4; ++e) {
        int col = c4 + e;
        float v;
        if (col < I_SZ)       v = inp2[(size_t)m * I_SZ + col];
        else if (col == I_SZ) v = 1.0f;
        else if (col < 513)   v = inp1[(size_t)m * I_SZ + (col - 257)];
        else                  v = 0.0f;
        h[e] = __float2half_rn(v);
    }
    uint2 u;
    u.x = *(uint32_t*)&h[0];
    u.y = *(uint32_t*)&h[2];
    *(uint2*)&g_Ab[(size_t)m * AB_K + c4] = u;
}

__global__ void __launch_bounds__(128)
reset_done()
{
    g_done[threadIdx.x] = 0;
}

// ---------------------------------------------------------------------------
// Fused kernel 1: 148 CTAs, all wave-1 co-resident (smem forces 1 CTA/SM).
//   bid <  128 : main GEMM (i<256, j<256), 512 thr, 2 warp-groups
//   bid >= 128 : border worker — loops over tiles, computes
//                g_Bord = [cext|a] @ Wb + b1, publishes per-tile flag.
// ---------------------------------------------------------------------------
extern __shared__ char smem1[];

__global__ void __launch_bounds__(512, 1)
fused_k1(const float* __restrict__ inp1, const float* __restrict__ inp2,
         const float* __restrict__ b1)
{
    const int bid  = blockIdx.x;
    const int tid  = threadIdx.x;
    const int lane = tid & 31;
    const int wid  = tid >> 5;
    const int gq   = lane >> 2;
    const int tig  = lane & 3;

    const int quad = lane >> 3, lrow = lane & 7;
    const int lmr  = (quad & 1) * 8 + lrow;
    const int lmc  = (quad >> 1) * 8;

    // =======================================================================
    // BORDER WORKER PATH
    // =======================================================================
    if (bid >= 128) {
        if (wid >= 8) return;          // warps 0..7 only (256 threads)
        const int worker = bid - 128;
        const int wm = wid & 3;
        const int wn = wid >> 2;
        const uint32_t sbase = smem_u32(smem1);

        for (int t = worker; t < 128; t += NWORK) {
            const int n0 = (t & 7) * BN;
            const int m0 = (t >> 3) * BM;

            auto issue = [&](int s, int buf) {
                const int k0 = s * 64;
                const uint32_t abase = sbase + (uint32_t)(buf * K2_BUF);
                #pragma unroll
                for (int q = 0; q < 4; ++q) {
                    int ch  = tid + q * 256;
                    int row = ch >> 3;
                    int c16 = ch & 7;
                    const __half* src = g_Ab + (size_t)(m0 + row) * AB_K + k0 + c16 * 8;
                    cpa16(abase + (uint32_t)(row * 144 + c16 * 16), src);
                }
                const uint32_t bbase = abase + K2_ABUF;
                #pragma unroll
                for (int q = 0; q < 2; ++q) {
                    int ch  = tid + q * 256;
                    int row = ch >> 3;
                    int c16 = ch & 7;
                    int kk  = k0 + row;
                    int grow;
                    if (kk < 257)      grow = 65792 + kk;
                    else if (kk < 513) grow = (kk - 257) * P_SZ + 256;
                    else               grow = 0;
                    const __half* src = g_W1h + (size_t)grow * N1 + n0 + c16 * 8;
                    cpa16(bbase + (uint32_t)(row * 144 + c16 * 16), src);
                }
            };

            float acc[2][4][4];
            #pragma unroll
            for (int mt = 0; mt < 2; ++mt)
                #pragma unroll
                for (int nt = 0; nt < 4; ++nt)
                    #pragma unroll
                    for (int r = 0; r < 4; ++r) acc[mt][nt][r] = 0.0f;

            issue(0, 0); cpcommit();
            issue(1, 1); cpcommit();

            int bufR = 0, bufW = 2;
            const int NST = AB_K / 64;   // 9

            for (int s = 0; s < NST; ++s) {
                cpwait1();
                bar_named(3);
                if (s + 2 < NST) issue(s + 2, bufW);
                cpcommit();

                const uint32_t abase = sbase + (uint32_t)(bufR * K2_BUF);
                const uint32_t bbase = abase + K2_ABUF;

                #pragma unroll
                for (int ks = 0; ks < 4; ++ks) {
                    uint32_t A[2][4];
                    #pragma unroll
                    for (int mt = 0; mt < 2; ++mt) {
                        uint32_t addr = abase + (uint32_t)(
                            (wm * 32 + mt * 16 + lmr) * 144 + (ks * 16 + lmc) * 2);
                        ldm_x4(A[mt][0], A[mt][1], A[mt][2], A[mt][3], addr);
                    }
                    #pragma unroll
                    for (int nh = 0; nh < 2; ++nh) {
                        uint32_t addr = bbase + (uint32_t)(
                            (ks * 16 + lmr) * 144 + (wn * 32 + nh * 16 + lmc) * 2);
                        uint32_t b0, b1r, b2r, b3;
                        ldm_x4t(b0, b1r, b2r, b3, addr);
                        #pragma unroll
                        for (int mt = 0; mt < 2; ++mt) {
                            mma16(acc[mt][nh * 2 + 0], A[mt][0], A[mt][1], A[mt][2], A[mt][3], b0, b1r);
                            mma16(acc[mt][nh * 2 + 1], A[mt][0], A[mt][1], A[mt][2], A[mt][3], b2r, b3);
                        }
                    }
                }
                bufR = (bufR == 2) ? 0 : bufR + 1;
                bufW = (bufW == 2) ? 0 : bufW + 1;
            }

            // epilogue: + b1, fp32 store to g_Bord
            #pragma unroll
            for (int mt = 0; mt < 2; ++mt)
                #pragma unroll
                for (int nt = 0; nt < 4; ++nt) {
                    int n_base = n0 + wn * 32 + nt * 8 + tig * 2;
                    float bv0 = b1[n_base], bv1 = b1[n_base + 1];
                    #pragma unroll
                    for (int h = 0; h < 2; ++h) {
                        int m = m0 + wm * 32 + mt * 16 + h * 8 + gq;
                        *(float2*)&g_Bord[(size_t)m * N1 + n_base] =
                            make_float2(acc[mt][nt][h * 2 + 0] + bv0,
                                        acc[mt][nt][h * 2 + 1] + bv1);
                    }
                }

            // publish: all writes visible, then flag
            __threadfence();
            bar_named(3);
            if (tid == 0) atomicExch(&g_done[t], 1);
            bar_named(3);   // keep warps together before next tile's issue
        }
        return;
    }

    // =======================================================================
    // MAIN PATH (128 CTAs)
    // =======================================================================
    const int grp  = wid >> 3;
    const int gtid = tid & 255;
    const int gwid = wid & 7;
    const int wm   = gwid & 3;
    const int wn   = gwid >> 2;
    const int n0   = (bid & 7) * BN;
    const int m0   = (bid >> 3) * BM;

    __half* c_s = (__half*)smem1;
    __half* b_s = (__half*)(smem1 + SMEM_C_BYTES);

    const int igbase = grp * NIG_G;
    const uint32_t c_base  = smem_u32(c_s);
    const uint32_t bring_u = smem_u32(b_s) + (uint32_t)(grp * 3 * BS_HALVES * 2);

    for (int idx = tid; idx < BM * 256; idx += 512) {
        int m = idx >> 8, j = idx & 255;
        c_s[m * CSTR + j] = __float2half_rn(inp2[(size_t)(m0 + m) * I_SZ + j]);
    }
    __syncthreads();

    auto issueW = [&](int igl, int kt, int buf) {
        int ig = igbase + igl;
        #pragma unroll
        for (int q = 0; q < 2; ++q) {
            int ch  = gtid + q * 256;
            int row = ch >> 3;
            int c16 = ch & 7;
            int i   = ig * 2 + (row >> 5);
            int grow = i * P_SZ + kt * 32 + (row & 31);
            const __half* src = g_W1h + (size_t)grow * N1 + n0 + c16 * 8;
            uint32_t dst = bring_u + (uint32_t)(buf * BS_HALVES * 2 + row * 144 + c16 * 16);
            cpa16(dst, src);
        }
    };

    float h_acc[2][4][4];
    #pragma unroll
    for (int mt = 0; mt < 2; ++mt)
        #pragma unroll
        for (int nt = 0; nt < 4; ++nt)
            #pragma unroll
            for (int r = 0; r < 4; ++r) h_acc[mt][nt][r] = 0.0f;

    issueW(0, 0, 0); cpcommit();
    issueW(0, 1, 1); cpcommit();

    int bufR = 0, bufW = 2;

    for (int igl = 0; igl < NIG_G; ++igl) {
        float av[2][4];
        #pragma unroll
        for (int g = 0; g < 2; ++g) {
            int i = (igbase + igl) * 2 + g;
            #pragma unroll
            for (int q = 0; q < 4; ++q) {
                int m = m0 + wm * 32 + (q >> 1) * 16 + (q & 1) * 8 + gq;
                av[g][q] = __ldg(&inp1[(size_t)m * I_SZ + i]);
            }
        }

        float tmp[2][2][4][4];
        #pragma unroll
        for (int g = 0; g < 2; ++g)
            #pragma unroll
            for (int mt = 0; mt < 2; ++mt)
                #pragma unroll
                for (int nt = 0; nt < 4; ++nt)
                    #pragma unroll
                    for (int q = 0; q < 4; ++q) tmp[g][mt][nt][q] = 0.0f;

        for (int kt = 0; kt < NKT; ++kt) {
            const int j0 = kt * 32;
            uint32_t A[2][2][4];
            #pragma unroll
            for (int ks = 0; ks < 2; ++ks)
                #pragma unroll
                for (int mt = 0; mt < 2; ++mt) {
                    uint32_t addr = c_base + 2u * (uint32_t)(
                        (wm * 32 + mt * 16 + lmr) * CSTR + j0 + ks * 16 + lmc);
                    ldm_x4(A[ks][mt][0], A[ks][mt][1], A[ks][mt][2], A[ks][mt][3], addr);
                }

            cpwait1();
            bar_named(grp + 1);

            // B fragments + MMAs first (critical path), prefetch after
            const uint32_t bb = bring_u + (uint32_t)(bufR * BS_HALVES * 2);
            #pragma unroll
            for (int g = 0; g < 2; ++g) {
                #pragma unroll
                for (int ks = 0; ks < 2; ++ks) {
                    #pragma unroll
                    for (int nh = 0; nh < 2; ++nh) {
                        uint32_t addr = bb + 2u * (uint32_t)(
                            (g * 32 + ks * 16 + lmr) * NSTR + wn * 32 + nh * 16 + lmc);
                        uint32_t b0, b1r, b2r, b3;
                        ldm_x4t(b0, b1r, b2r, b3, addr);
                        #pragma unroll
                        for (int mt = 0; mt < 2; ++mt) {
                            mma16(tmp[g][mt][nh * 2 + 0],
                                  A[ks][mt][0], A[ks][mt][1], A[ks][mt][2], A[ks][mt][3],
                                  b0, b1r);
                            mma16(tmp[g][mt][nh * 2 + 1],
                                  A[ks][mt][0], A[ks][mt][1], A[ks][mt][2], A[ks][mt][3],
                                  b2r, b3);
                        }
                    }
                }
            }

            int kt2 = kt + 2, ig2 = igl;
            if (kt2 >= NKT) { kt2 -= NKT; ++ig2; }
            if (ig2 < NIG_G) issueW(ig2, kt2, bufW);
            cpcommit();

            bufR = (bufR == 2) ? 0 : bufR + 1;
            bufW = (bufW == 2) ? 0 : bufW + 1;
        }

        #pragma unroll
        for (int g = 0; g < 2; ++g)
            #pragma unroll
            for (int mt = 0; mt < 2; ++mt)
                #pragma unroll
                for (int nt = 0; nt < 4; ++nt)
                    #pragma unroll
                    for (int q = 0; q < 4; ++q)
                        h_acc[mt][nt][q] += av[g][mt * 2 + (q >> 1)] * tmp[g][mt][nt][q];
    }

    // ---- wait for this tile's border partial (producers co-resident) ----
    if (tid == 0) {
        while (atomicAdd(&g_done[bid], 0) == 0) { __nanosleep(64); }
    }
    __syncthreads();

    // ---- cross-group reduce through retired c_s region ----
    float* xbuf = (float*)smem1;
    if (grp == 1) {
        #pragma unroll
        for (int mt = 0; mt < 2; ++mt)
            #pragma unroll
            for (int nt = 0; nt < 4; ++nt)
                *(float4*)&xbuf[gtid * 36 + (mt * 4 + nt) * 4] =
                    make_float4(h_acc[mt][nt][0], h_acc[mt][nt][1],
                                h_acc[mt][nt][2], h_acc[mt][nt][3]);
    }
    __syncthreads();
    if (grp == 0) {
        #pragma unroll
        for (int mt = 0; mt < 2; ++mt)
            #pragma unroll
            for (int nt = 0; nt < 4; ++nt) {
                float4 p = *(const float4*)&xbuf[gtid * 36 + (mt * 4 + nt) * 4];
                h_acc[mt][nt][0] += p.x; h_acc[mt][nt][1] += p.y;
                h_acc[mt][nt][2] += p.z; h_acc[mt][nt][3] += p.w;

                int n_base = n0 + wn * 32 + nt * 8 + tig * 2;
                #pragma unroll
                for (int h = 0; h < 2; ++h) {
                    int m = m0 + wm * 32 + mt * 16 + h * 8 + gq;
                    const float2* bp = (const float2*)&g_Bord[(size_t)m * N1 + n_base];
                    float2 bo;
                    bo.x = __ldcg(&bp->x);
                    bo.y = __ldcg(&bp->y);
                    float v0 = fmaxf(h_acc[mt][nt][h * 2 + 0] + bo.x, 0.0f);
                    float v1 = fmaxf(h_acc[mt][nt][h * 2 + 1] + bo.y, 0.0f);
                    __half2 hv = __floats2half2_rn(v0, v1);
                    *(__half2*)&g_Hh[(size_t)m * N1 + n_base] = hv;
                }
            }
    }
}

// ---------------------------------------------------------------------------
// Kernel 2: out = relu( H @ W2 + b2 ) — fp16 tensor-core, fp32 accum.
// ---------------------------------------------------------------------------
extern __shared__ char smem2[];

__global__ void __launch_bounds__(256, 1)
fused_k2(const float* __restrict__ b2, float* __restrict__ out)
{
    const int tid  = threadIdx.x;
    const int lane = tid & 31;
    const int wid  = tid >> 5;
    const int wm   = wid & 3;
    const int wn   = wid >> 2;
    const int gq   = lane >> 2;
    const int tig  = lane & 3;
    const int m0   = blockIdx.y * BM;
    const int n0   = blockIdx.x * BN;

    const uint32_t sbase = smem_u32(smem2);
    const int quad = lane >> 3, lrow = lane & 7;
    const int lmr  = (quad & 1) * 8 + lrow;
    const int lmc  = (quad >> 1) * 8;

    auto issue = [&](int s, int buf) {
        const int k0 = s * 64;
        const uint32_t abase = sbase + (uint32_t)(buf * K2_BUF);
        #pragma unroll
        for (int q = 0; q < 4; ++q) {
            int ch  = tid + q * 256;
            int row = ch >> 3;
            int c16 = ch & 7;
            const __half* src = g_Hh + (size_t)(m0 + row) * N1 + k0 + c16 * 8;
            cpa16(abase + (uint32_t)(row * 144 + c16 * 16), src);
        }
        const uint32_t bbase = abase + K2_ABUF;
        #pragma unroll
        for (int q = 0; q < 2; ++q) {
            int ch  = tid + q * 256;
            int row = ch >> 3;
            int c16 = ch & 7;
            const __half* src = g_W2h + (size_t)(k0 + row) * N1 + n0 + c16 * 8;
            cpa16(bbase + (uint32_t)(row * 144 + c16 * 16), src);
        }
    };

    float acc[2][4][4];
    #pragma unroll
    for (int mt = 0; mt < 2; ++mt)
        #pragma unroll
        for (int nt = 0; nt < 4; ++nt)
            #pragma unroll
            for (int r = 0; r < 4; ++r) acc[mt][nt][r] = 0.0f;

    issue(0, 0); cpcommit();
    issue(1, 1); cpcommit();

    int bufR = 0, bufW = 2;
    const int NST = N1 / 64;

    for (int s = 0; s < NST; ++s) {
        cpwait1();
        __syncthreads();
        if (s + 2 < NST) issue(s + 2, bufW);
        cpcommit();

        const uint32_t abase = sbase + (uint32_t)(bufR * K2_BUF);
        const uint32_t bbase = abase + K2_ABUF;

        #pragma unroll
        for (int ks = 0; ks < 4; ++ks) {
            uint32_t A[2][4];
            #pragma unroll
            for (int mt = 0; mt < 2; ++mt) {
                uint32_t addr = abase + (uint32_t)(
                    (wm * 32 + mt * 16 + lmr) * 144 + (ks * 16 + lmc) * 2);
                ldm_x4(A[mt][0], A[mt][1], A[mt][2], A[mt][3], addr);
            }
            #pragma unroll
            for (int nh = 0; nh < 2; ++nh) {
                uint32_t addr = bbase + (uint32_t)(
                    (ks * 16 + lmr) * 144 + (wn * 32 + nh * 16 + lmc) * 2);
                uint32_t b0, b1, b2, b3;
                ldm_x4t(b0, b1, b2, b3, addr);
                #pragma unroll
                for (int mt = 0; mt < 2; ++mt) {
                    mma16(acc[mt][nh * 2 + 0], A[mt][0], A[mt][1], A[mt][2], A[mt][3], b0, b1);
                    mma16(acc[mt][nh * 2 + 1], A[mt][0], A[mt][1], A[mt][2], A[mt][3], b2, b3);
                }
            }
        }
        bufR = (bufR == 2) ? 0 : bufR + 1;
        bufW = (bufW == 2) ? 0 : bufW + 1;
    }

    #pragma unroll
    for (int mt = 0; mt < 2; ++mt)
        #pragma unroll
        for (int nt = 0; nt < 4; ++nt) {
            int n_base = n0 + wn * 32 + nt * 8 + tig * 2;
            float bv0 = b2[n_base], bv1 = b2[n_base + 1];
            #pragma unroll
            for (int h = 0; h < 2; ++h) {
                int m = m0 + wm * 32 + mt * 16 + h * 8 + gq;
                float v0 = fmaxf(acc[mt][nt][h * 2 + 0] + bv0, 0.0f);
                float v1 = fmaxf(acc[mt][nt][h * 2 + 1] + bv1, 0.0f);
                *(float2*)&out[(size_t)m * N1 + n_base] = make_float2(v0, v1);
            }
        }
}

// ---------------------------------------------------------------------------
extern "C" void kernel_launch(void* const* d_in, const int* in_sizes, int n_in,
                              void* d_out, int out_size)
{
    const float* inp1 = (const float*)d_in[0];
    const float* inp2 = (const float*)d_in[1];
    const float* W1   = (const float*)d_in[2];
    const float* b1   = (const float*)d_in[3];
    const float* W2   = (const float*)d_in[4];
    const float* b2   = (const float*)d_in[5];
    (void)in_sizes; (void)n_in; (void)out_size;

    convW<<<16513, 256>>>(W1);
    convW2<<<128, 256>>>(W2);
    convA<<<(B_SZ * (AB_K / 4)) / 256, 256>>>(inp1, inp2);
    reset_done<<<1, 128>>>();

    cudaFuncSetAttribute(fused_k1, cudaFuncAttributeMaxDynamicSharedMemorySize, SMEM_TOTAL);
    fused_k1<<<148, 512, SMEM_TOTAL>>>(inp1, inp2, b1);

    cudaFuncSetAttribute(fused_k2, cudaFuncAttributeMaxDynamicSharedMemorySize, K2_SMEM);
    fused_k2<<<dim3(N1 / BN, B_SZ / BM), 256, K2_SMEM>>>(b2, (float*)d_out);
}